// round 15
// baseline (speedup 1.0000x reference)
#include <cuda_runtime.h>
#include <math.h>
#include <cstdint>

// ---------------------------------------------------------------------------
// GPT forward. GEMMs + attention via warp-level tf32 mma.sync (sm_80 PTX --
// compiles on plain sm_103 target; tcgen05 rejected by this harness's ptxas).
// R14 changes (pure scheduling, zero numeric delta):
//   1) wide GEMM: single-sync double-buffer (1 bar.sync per K-chunk, was 2)
//   2) attention: big-tiles-first launch order (LPT tail-wave balance)
// B=2, S=2048 (4096 tokens), D=512, H=8, HD=64, FF=2048, L=4, V=50257.
// ---------------------------------------------------------------------------

#define NTOK   4096
#define DMODEL 512
#define NLAYER 4
#define NHEAD  8
#define HDIM   64
#define FFDIM  2048
#define SEQ    2048
#define VOCAB  50257

__device__ float g_x[NTOK * DMODEL];
__device__ float g_h[NTOK * DMODEL];
__device__ float g_qkv[NTOK * 3 * DMODEL];
__device__ float g_o[NTOK * DMODEL];
__device__ float g_ff[NTOK * FFDIM];
// Pre-rounded (tf32) weights scratch: Wqkv | Wproj | Wfc | Wfc2 | wte
#define WOFF_QKV  0
#define WOFF_PROJ 3145728
#define WOFF_FC   4194304
#define WOFF_FC2  8388608
#define WOFF_WTE  12582912
#define WTOTAL    38314496
__device__ float g_w[WTOTAL];

// ---------------------------------------------------------------------------
// tf32 / cp.async helpers
// ---------------------------------------------------------------------------
__device__ __forceinline__ float rtf32(float x) {
    uint32_t u;
    asm("cvt.rna.tf32.f32 %0, %1;" : "=r"(u) : "f"(x));
    return __uint_as_float(u);
}

__device__ __forceinline__ float4 rtf32x4(float4 v) {
    uint32_t a, b, c, d;
    asm("cvt.rna.tf32.f32 %0, %1;" : "=r"(a) : "f"(v.x));
    asm("cvt.rna.tf32.f32 %0, %1;" : "=r"(b) : "f"(v.y));
    asm("cvt.rna.tf32.f32 %0, %1;" : "=r"(c) : "f"(v.z));
    asm("cvt.rna.tf32.f32 %0, %1;" : "=r"(d) : "f"(v.w));
    v.x = __uint_as_float(a); v.y = __uint_as_float(b);
    v.z = __uint_as_float(c); v.w = __uint_as_float(d);
    return v;
}

__device__ __forceinline__ void mma_tf32(float* d, const uint32_t* a,
                                         const uint32_t* b) {
    asm volatile(
        "mma.sync.aligned.m16n8k8.row.col.f32.tf32.tf32.f32 "
        "{%0,%1,%2,%3}, {%4,%5,%6,%7}, {%8,%9}, {%0,%1,%2,%3};"
        : "+f"(d[0]), "+f"(d[1]), "+f"(d[2]), "+f"(d[3])
        : "r"(a[0]), "r"(a[1]), "r"(a[2]), "r"(a[3]),
          "r"(b[0]), "r"(b[1]));
}

__device__ __forceinline__ void mma_tf32_b(float* d, const uint32_t* a,
                                           uint32_t b0, uint32_t b1) {
    asm volatile(
        "mma.sync.aligned.m16n8k8.row.col.f32.tf32.tf32.f32 "
        "{%0,%1,%2,%3}, {%4,%5,%6,%7}, {%8,%9}, {%0,%1,%2,%3};"
        : "+f"(d[0]), "+f"(d[1]), "+f"(d[2]), "+f"(d[3])
        : "r"(a[0]), "r"(a[1]), "r"(a[2]), "r"(a[3]),
          "r"(b0), "r"(b1));
}

__device__ __forceinline__ uint32_t cvsm(const void* p) {
    return (uint32_t)__cvta_generic_to_shared(p);
}
#define CP_A16(dst, src) \
    asm volatile("cp.async.ca.shared.global [%0], [%1], 16;" \
                 :: "r"(dst), "l"(src))
#define CP_A16Z(dst, src, sb) \
    asm volatile("cp.async.ca.shared.global [%0], [%1], 16, %2;" \
                 :: "r"(dst), "l"(src), "r"(sb))
#define CP_COMMIT() asm volatile("cp.async.commit_group;")
#define CP_WAIT(n)  asm volatile("cp.async.wait_group %0;" :: "n"(n))

// ---------------------------------------------------------------------------
// Pre-round copy: dst[i] = tf32(src[i]), float4 grid-stride
// ---------------------------------------------------------------------------
__global__ void rcopy_kernel(const float* __restrict__ src,
                             float* __restrict__ dst, int n4) {
    int i = blockIdx.x * 256 + threadIdx.x;
    int stride = gridDim.x * 256;
    for (; i < n4; i += stride) {
        float4 v = *(const float4*)(src + (size_t)i * 4);
        *(float4*)(dst + (size_t)i * 4) = rtf32x4(v);
    }
}

// ---------------------------------------------------------------------------
// Embedding
// ---------------------------------------------------------------------------
__global__ void embed_kernel(const int* __restrict__ idx,
                             const float* __restrict__ wte,
                             const float* __restrict__ wpe,
                             float* __restrict__ x) {
    int i = blockIdx.x * 256 + threadIdx.x;
    int tok = i >> 9;
    int d   = i & 511;
    int s   = tok & (SEQ - 1);
    x[i] = wte[(size_t)idx[tok] * DMODEL + d] + wpe[s * DMODEL + d];
}

// ---------------------------------------------------------------------------
// LayerNorm over last dim (512); output tf32-rounded (consumed only as GEMM A)
// ---------------------------------------------------------------------------
__global__ void ln_kernel(const float* __restrict__ x,
                          const float* __restrict__ w,
                          const float* __restrict__ b,
                          float* __restrict__ out) {
    int row = blockIdx.x;
    int tid = threadIdx.x;
    const float* xr = x + (size_t)row * DMODEL;
    float v0 = xr[tid];
    float v1 = xr[tid + 256];
    float s  = v0 + v1;
    float sq = v0 * v0 + v1 * v1;
    #pragma unroll
    for (int off = 16; off >= 1; off >>= 1) {
        s  += __shfl_xor_sync(0xffffffffu, s,  off);
        sq += __shfl_xor_sync(0xffffffffu, sq, off);
    }
    __shared__ float ss[8], ssq[8];
    int warp = tid >> 5, lane = tid & 31;
    if (lane == 0) { ss[warp] = s; ssq[warp] = sq; }
    __syncthreads();
    float ts = 0.f, tq = 0.f;
    #pragma unroll
    for (int wI = 0; wI < 8; wI++) { ts += ss[wI]; tq += ssq[wI]; }
    float mean = ts * (1.0f / DMODEL);
    float var  = tq * (1.0f / DMODEL) - mean * mean;
    float rstd = rsqrtf(var + 1e-5f);
    float* outr = out + (size_t)row * DMODEL;
    outr[tid]       = rtf32((v0 - mean) * rstd * w[tid]       + b[tid]);
    outr[tid + 256] = rtf32((v1 - mean) * rstd * w[tid + 256] + b[tid + 256]);
}

#define EPI_BIAS 0
#define EPI_GELU 1
#define EPI_RES  2
#define EPI_NONE 3
#define EPI_QKV  4

// ---------------------------------------------------------------------------
// WIDE tf32 GEMM: CTA 128x256, 8 warps (2m x 4n) at 64x64 each, K chunk 32,
// cp.async double-buffered with ONE bar.sync per chunk:
//   loop: wait(stage ch) -> sync (data visible AND buffer !b free) ->
//         issue stage(ch+1) into !b -> compute b.
//   TRANSB=false: B [K,N] row-major, N % 256 == 0.  (QKV, FC1)
//   TRANSB=true : B [N,K] row-major, N guarded.     (lm_head)
// EPI_GELU output tf32-rounded (feeds FC2 A). EPI_QKV rounds cols<1024 (q,k).
// ---------------------------------------------------------------------------
#define WGEMM_SMEM 110592

template<bool TRANSB, int EPI>
__global__ __launch_bounds__(256)
void wgemm_kernel(const float* __restrict__ A, const float* __restrict__ B,
                  const float* __restrict__ bias, const float* __restrict__ R,
                  float* __restrict__ C, int M, int N, int K) {
    extern __shared__ float wsm[];
    float* const As0 = wsm;
    float* const As1 = wsm + 4608;
    float* const Bs0 = wsm + 9216;
    float* const Bs1 = wsm + 18432;

    const int tid  = threadIdx.x;
    const int lane = tid & 31;
    const int warp = tid >> 5;
    const int wm   = warp & 1;
    const int wn   = warp >> 1;
    const int grp  = lane >> 2;
    const int tig  = lane & 3;
    const int m0   = blockIdx.x * 128;
    const int n0   = blockIdx.y * 256;

    float acc[4][8][4];
    #pragma unroll
    for (int i = 0; i < 4; i++)
        #pragma unroll
        for (int j = 0; j < 8; j++)
            #pragma unroll
            for (int r = 0; r < 4; r++) acc[i][j][r] = 0.f;

    const int nchunk = K >> 5;

    auto stage = [&](int ch, float* As, float* Bs) {
        {
            const int row = tid >> 1;
            const int f4b = (tid & 1) * 4;
            const float* g = A + (size_t)(m0 + row) * K + ch * 32 + f4b * 4;
            uint32_t s = cvsm(&As[row * 36 + f4b * 4]);
            #pragma unroll
            for (int u = 0; u < 4; u++)
                CP_A16(s + u * 16, g + u * 4);
        }
        if (!TRANSB) {
            const int n4  = tid & 31;
            const int kr0 = tid >> 5;
            #pragma unroll
            for (int u = 0; u < 4; u++) {
                int kr = kr0 + u * 8;
                const float* g = B + (size_t)(ch * 32 + kr) * N + n0 + n4 * 4;
                uint32_t s = cvsm(&Bs[kr * 264 + n4 * 4]);
                CP_A16(s, g);
                CP_A16(s + 512, g + 128);
            }
        } else {
            #pragma unroll
            for (int h = 0; h < 2; h++) {
                int nr = (tid >> 1) + h * 128;
                int gn = n0 + nr;
                uint32_t sb  = (gn < N) ? 16u : 0u;
                int      gnc = (gn < N) ? gn : 0;
                const int f4b = (tid & 1) * 4;
                const float* g = B + (size_t)gnc * K + ch * 32 + f4b * 4;
                uint32_t s = cvsm(&Bs[nr * 36 + f4b * 4]);
                #pragma unroll
                for (int u = 0; u < 4; u++)
                    CP_A16Z(s + u * 16, g + u * 4, sb);
            }
        }
    };

    stage(0, As0, Bs0);
    CP_COMMIT();

    #pragma unroll 1
    for (int ch = 0; ch < nchunk; ch++) {
        const int b = ch & 1;
        float* As = b ? As1 : As0;
        float* Bs = b ? Bs1 : Bs0;
        CP_WAIT(0);          // stage(ch) resident
        __syncthreads();     // data visible to all; all done with buffer !b
        if (ch + 1 < nchunk) {
            stage(ch + 1, b ? As0 : As1, b ? Bs0 : Bs1);
            CP_COMMIT();
        }

        #pragma unroll
        for (int ks = 0; ks < 4; ks++) {
            const int c = ks * 8 + tig;
            uint32_t af[4][4];
            #pragma unroll
            for (int mf = 0; mf < 4; mf++) {
                int r = wm * 64 + mf * 16 + grp;
                af[mf][0] = __float_as_uint(As[r * 36 + c]);
                af[mf][1] = __float_as_uint(As[(r + 8) * 36 + c]);
                af[mf][2] = __float_as_uint(As[r * 36 + c + 4]);
                af[mf][3] = __float_as_uint(As[(r + 8) * 36 + c + 4]);
            }
            uint32_t bf[8][2];
            #pragma unroll
            for (int nf = 0; nf < 8; nf++) {
                int n = wn * 64 + nf * 8 + grp;
                if (!TRANSB) {
                    bf[nf][0] = __float_as_uint(Bs[c * 264 + n]);
                    bf[nf][1] = __float_as_uint(Bs[(c + 4) * 264 + n]);
                } else {
                    bf[nf][0] = __float_as_uint(Bs[n * 36 + c]);
                    bf[nf][1] = __float_as_uint(Bs[n * 36 + c + 4]);
                }
            }
            #pragma unroll
            for (int mf = 0; mf < 4; mf++)
                #pragma unroll
                for (int nf = 0; nf < 8; nf++)
                    mma_tf32(acc[mf][nf], af[mf], bf[nf]);
        }
    }

    #pragma unroll
    for (int mf = 0; mf < 4; mf++) {
        #pragma unroll
        for (int half = 0; half < 2; half++) {
            int row = m0 + wm * 64 + mf * 16 + grp + half * 8;
            size_t ro = (size_t)row * N;
            #pragma unroll
            for (int nf = 0; nf < 8; nf++) {
                int col = n0 + wn * 64 + nf * 8 + tig * 2;
                float v0 = acc[mf][nf][half * 2 + 0];
                float v1 = acc[mf][nf][half * 2 + 1];
                if (EPI != EPI_NONE) { v0 += bias[col]; v1 += bias[col + 1]; }
                if (EPI == EPI_QKV) {
                    if (col < 1024) { v0 = rtf32(v0); v1 = rtf32(v1); }
                }
                if (EPI == EPI_GELU) {
                    v0 = rtf32(0.5f * v0 * (1.0f + erff(v0 * 0.70710678118654752f)));
                    v1 = rtf32(0.5f * v1 * (1.0f + erff(v1 * 0.70710678118654752f)));
                }
                if (EPI == EPI_RES) { v0 += R[ro + col]; v1 += R[ro + col + 1]; }
                if (!TRANSB) {
                    C[ro + col]     = v0;
                    C[ro + col + 1] = v1;
                } else {
                    if (col < N)     C[ro + col]     = v0;
                    if (col + 1 < N) C[ro + col + 1] = v1;
                }
            }
        }
    }
}

// ---------------------------------------------------------------------------
// NARROW tf32 GEMM: CTA 128x128, N=512 GEMMs. Operands pre-rounded.
// ---------------------------------------------------------------------------
template<int EPI>
__global__ __launch_bounds__(256)
void mma_gemm_kernel(const float* __restrict__ A, const float* __restrict__ B,
                     const float* __restrict__ bias, const float* __restrict__ R,
                     float* __restrict__ C, int M, int N, int K) {
    __shared__ float As[32][136];
    __shared__ float Bs[32][136];

    const int tid  = threadIdx.x;
    const int lane = tid & 31;
    const int wid  = tid >> 5;
    const int wm   = wid & 1;
    const int wn   = wid >> 1;
    const int m0   = blockIdx.x * 128;
    const int n0   = blockIdx.y * 128;

    const int tig  = lane & 3;
    const int grp  = lane >> 2;

    float acc[4][4][4];
    #pragma unroll
    for (int i = 0; i < 4; i++)
        #pragma unroll
        for (int j = 0; j < 4; j++)
            #pragma unroll
            for (int r = 0; r < 4; r++) acc[i][j][r] = 0.f;

    const int st_r  = tid >> 1;
    const int st_k0 = (tid & 1) * 16;
    const int bq_n  = (tid & 31) * 4;
    const int bq_k  = tid >> 5;

    const int nchunk = K >> 5;

    float4 pa[4], pb[4];

    {
        const float* Ap = A + (size_t)(m0 + st_r) * K + st_k0;
        #pragma unroll
        for (int u = 0; u < 4; u++)
            pa[u] = *(const float4*)(Ap + u * 4);
        #pragma unroll
        for (int u = 0; u < 4; u++)
            pb[u] = *(const float4*)(B + (size_t)(u * 8 + bq_k) * N + n0 + bq_n);
    }

    #pragma unroll 1
    for (int ch = 0; ch < nchunk; ch++) {
        __syncthreads();
        #pragma unroll
        for (int u = 0; u < 4; u++) {
            float4 av = pa[u];
            int k = st_k0 + u * 4;
            As[k + 0][st_r] = av.x;
            As[k + 1][st_r] = av.y;
            As[k + 2][st_r] = av.z;
            As[k + 3][st_r] = av.w;
            *(float4*)&Bs[u * 8 + bq_k][bq_n] = pb[u];
        }
        __syncthreads();

        if (ch + 1 < nchunk) {
            const int k0 = (ch + 1) * 32;
            const float* Ap = A + (size_t)(m0 + st_r) * K + k0 + st_k0;
            #pragma unroll
            for (int u = 0; u < 4; u++)
                pa[u] = *(const float4*)(Ap + u * 4);
            #pragma unroll
            for (int u = 0; u < 4; u++)
                pb[u] = *(const float4*)(B + (size_t)(k0 + u * 8 + bq_k) * N + n0 + bq_n);
        }

        #pragma unroll
        for (int ks = 0; ks < 4; ks++) {
            const int c = ks * 8 + tig;
            uint32_t af[4][4];
            #pragma unroll
            for (int mf = 0; mf < 4; mf++) {
                int r = wm * 64 + mf * 16 + grp;
                af[mf][0] = __float_as_uint(As[c][r]);
                af[mf][1] = __float_as_uint(As[c][r + 8]);
                af[mf][2] = __float_as_uint(As[c + 4][r]);
                af[mf][3] = __float_as_uint(As[c + 4][r + 8]);
            }
            uint32_t bf[4][2];
            #pragma unroll
            for (int nf = 0; nf < 4; nf++) {
                int n = wn * 32 + nf * 8 + grp;
                bf[nf][0] = __float_as_uint(Bs[c][n]);
                bf[nf][1] = __float_as_uint(Bs[c + 4][n]);
            }
            #pragma unroll
            for (int mf = 0; mf < 4; mf++)
                #pragma unroll
                for (int nf = 0; nf < 4; nf++)
                    mma_tf32(acc[mf][nf], af[mf], bf[nf]);
        }
    }

    #pragma unroll
    for (int mf = 0; mf < 4; mf++) {
        #pragma unroll
        for (int half = 0; half < 2; half++) {
            int row = m0 + wm * 64 + mf * 16 + grp + half * 8;
            size_t ro = (size_t)row * N;
            #pragma unroll
            for (int nf = 0; nf < 4; nf++) {
                int col = n0 + wn * 32 + nf * 8 + tig * 2;
                float v0 = acc[mf][nf][half * 2 + 0];
                float v1 = acc[mf][nf][half * 2 + 1];
                v0 += bias[col]; v1 += bias[col + 1];
                if (EPI == EPI_RES) { v0 += R[ro + col]; v1 += R[ro + col + 1]; }
                C[ro + col]     = v0;
                C[ro + col + 1] = v1;
            }
        }
    }
}

// ---------------------------------------------------------------------------
// Causal flash attention v1 via tf32 mma.sync; big q-tiles launch FIRST.
// CTA = 64 q-rows x head x batch; 128 threads = 4 warps; 2 CTAs/SM.
// q,k arrive PRE-ROUNDED from the QKV epilogue. V staged hi/lo.
// ---------------------------------------------------------------------------
#define ATTN_SMEM 89088   // 22272 floats

__global__ __launch_bounds__(128)
void attn_mma_kernel(const float* __restrict__ qkv, float* __restrict__ o) {
    extern __shared__ float sm[];
    float* Ks = sm;              // [64][68]
    float* Vh = sm + 4352;       // [64][72]
    float* Vl = sm + 8960;       // [64][72]
    float* Ph = sm + 13568;      // [64][68]
    float* Pl = sm + 17920;      // [64][68]

    const int tid  = threadIdx.x;
    const int lane = tid & 31;
    const int warp = tid >> 5;
    const int grp  = lane >> 2;
    const int tig  = lane & 3;
    const int qb = (int)gridDim.x - 1 - (int)blockIdx.x;   // big tiles first
    const int hh = blockIdx.y, bb = blockIdx.z;
    const int q0 = qb * 64;
    const size_t tokbase = (size_t)bb * SEQ;

    #pragma unroll
    for (int u = 0; u < 8; u++) {
        int idx = u * 128 + tid;
        int r = idx >> 4;
        int c = (idx & 15) << 2;
        const float* src = qkv + (tokbase + q0 + r) * 1536 + hh * 64 + c;
        *(float4*)&Ks[r * 68 + c] = *(const float4*)src;
    }
    __syncthreads();

    // Q fragments: already tf32 (rounded at QKV epilogue)
    uint32_t qa[8][4];
    {
        const int r0 = (warp * 16 + grp) * 68;
        const int r1 = r0 + 8 * 68;
        #pragma unroll
        for (int kf = 0; kf < 8; kf++) {
            int c = kf * 8 + tig;
            qa[kf][0] = __float_as_uint(Ks[r0 + c]);
            qa[kf][1] = __float_as_uint(Ks[r1 + c]);
            qa[kf][2] = __float_as_uint(Ks[r0 + c + 4]);
            qa[kf][3] = __float_as_uint(Ks[r1 + c + 4]);
        }
    }

    float m0 = -1e30f, m1 = -1e30f, l0 = 0.f, l1 = 0.f;
    float oacc[8][4];
    #pragma unroll
    for (int nf = 0; nf < 8; nf++)
        #pragma unroll
        for (int c = 0; c < 4; c++) oacc[nf][c] = 0.f;

    const int prow0 = (warp * 16 + grp) * 68;
    const int prow1 = prow0 + 8 * 68;
    const int row0g = q0 + warp * 16 + grp;
    const int row1g = row0g + 8;

    #pragma unroll 1
    for (int kb = 0; kb <= qb; kb++) {
        const int k0 = kb * 64;
        __syncthreads();
        // K already tf32 (rounded at QKV epilogue): plain copy. V: hi/lo.
        #pragma unroll
        for (int u = 0; u < 8; u++) {
            int idx = u * 128 + tid;
            int r = idx >> 4;
            int c = (idx & 15) << 2;
            const float* kp = qkv + (tokbase + k0 + r) * 1536 + 512 + hh * 64 + c;
            *(float4*)&Ks[r * 68 + c] = *(const float4*)kp;
            const float* vp = qkv + (tokbase + k0 + r) * 1536 + 1024 + hh * 64 + c;
            float4 v  = *(const float4*)vp;
            float4 vh = rtf32x4(v);
            float4 vl;
            vl.x = v.x - vh.x; vl.y = v.y - vh.y;
            vl.z = v.z - vh.z; vl.w = v.w - vh.w;
            vl = rtf32x4(vl);
            *(float4*)&Vh[r * 72 + c] = vh;
            *(float4*)&Vl[r * 72 + c] = vl;
        }
        __syncthreads();

        float sacc[8][4];
        #pragma unroll
        for (int nf = 0; nf < 8; nf++) {
            #pragma unroll
            for (int c = 0; c < 4; c++) sacc[nf][c] = 0.f;
            const int kb_row = (nf * 8 + grp) * 68;
            #pragma unroll
            for (int kf = 0; kf < 8; kf++) {
                uint32_t b0 = __float_as_uint(Ks[kb_row + kf * 8 + tig]);
                uint32_t b1 = __float_as_uint(Ks[kb_row + kf * 8 + tig + 4]);
                mma_tf32_b(sacc[nf], qa[kf], b0, b1);
            }
        }

        const float scale = 0.125f;
        #pragma unroll
        for (int nf = 0; nf < 8; nf++) {
            int colb = k0 + nf * 8 + 2 * tig;
            sacc[nf][0] = (colb     > row0g) ? -1e30f : sacc[nf][0] * scale;
            sacc[nf][1] = (colb + 1 > row0g) ? -1e30f : sacc[nf][1] * scale;
            sacc[nf][2] = (colb     > row1g) ? -1e30f : sacc[nf][2] * scale;
            sacc[nf][3] = (colb + 1 > row1g) ? -1e30f : sacc[nf][3] * scale;
        }

        float rm0 = -1e30f, rm1 = -1e30f;
        #pragma unroll
        for (int nf = 0; nf < 8; nf++) {
            rm0 = fmaxf(rm0, fmaxf(sacc[nf][0], sacc[nf][1]));
            rm1 = fmaxf(rm1, fmaxf(sacc[nf][2], sacc[nf][3]));
        }
        rm0 = fmaxf(rm0, __shfl_xor_sync(0xffffffffu, rm0, 1));
        rm0 = fmaxf(rm0, __shfl_xor_sync(0xffffffffu, rm0, 2));
        rm1 = fmaxf(rm1, __shfl_xor_sync(0xffffffffu, rm1, 1));
        rm1 = fmaxf(rm1, __shfl_xor_sync(0xffffffffu, rm1, 2));
        float nm0 = fmaxf(m0, rm0), nm1 = fmaxf(m1, rm1);
        float corr0 = __expf(m0 - nm0), corr1 = __expf(m1 - nm1);
        float rs0 = 0.f, rs1 = 0.f;
        #pragma unroll
        for (int nf = 0; nf < 8; nf++) {
            float p0 = __expf(sacc[nf][0] - nm0);
            float p1 = __expf(sacc[nf][1] - nm0);
            float p2 = __expf(sacc[nf][2] - nm1);
            float p3 = __expf(sacc[nf][3] - nm1);
            rs0 += p0 + p1; rs1 += p2 + p3;
            sacc[nf][0] = p0; sacc[nf][1] = p1;
            sacc[nf][2] = p2; sacc[nf][3] = p3;
        }
        rs0 += __shfl_xor_sync(0xffffffffu, rs0, 1);
        rs0 += __shfl_xor_sync(0xffffffffu, rs0, 2);
        rs1 += __shfl_xor_sync(0xffffffffu, rs1, 1);
        rs1 += __shfl_xor_sync(0xffffffffu, rs1, 2);
        l0 = l0 * corr0 + rs0;  m0 = nm0;
        l1 = l1 * corr1 + rs1;  m1 = nm1;
        #pragma unroll
        for (int nf = 0; nf < 8; nf++) {
            oacc[nf][0] *= corr0; oacc[nf][1] *= corr0;
            oacc[nf][2] *= corr1; oacc[nf][3] *= corr1;
        }

        #pragma unroll
        for (int nf = 0; nf < 8; nf++) {
            int cc = nf * 8 + 2 * tig;
            float ph, pl;
            ph = rtf32(sacc[nf][0]); pl = rtf32(sacc[nf][0] - ph);
            Ph[prow0 + cc] = ph; Pl[prow0 + cc] = pl;
            ph = rtf32(sacc[nf][1]); pl = rtf32(sacc[nf][1] - ph);
            Ph[prow0 + cc + 1] = ph; Pl[prow0 + cc + 1] = pl;
            ph = rtf32(sacc[nf][2]); pl = rtf32(sacc[nf][2] - ph);
            Ph[prow1 + cc] = ph; Pl[prow1 + cc] = pl;
            ph = rtf32(sacc[nf][3]); pl = rtf32(sacc[nf][3] - ph);
            Ph[prow1 + cc + 1] = ph; Pl[prow1 + cc + 1] = pl;
        }
        __syncwarp();

        #pragma unroll
        for (int kf = 0; kf < 8; kf++) {
            uint32_t ah[4], al[4];
            int c = kf * 8 + tig;
            ah[0] = __float_as_uint(Ph[prow0 + c]);
            ah[1] = __float_as_uint(Ph[prow1 + c]);
            ah[2] = __float_as_uint(Ph[prow0 + c + 4]);
            ah[3] = __float_as_uint(Ph[prow1 + c + 4]);
            al[0] = __float_as_uint(Pl[prow0 + c]);
            al[1] = __float_as_uint(Pl[prow1 + c]);
            al[2] = __float_as_uint(Pl[prow0 + c + 4]);
            al[3] = __float_as_uint(Pl[prow1 + c + 4]);
            const int vr0 = (kf * 8 + tig) * 72;
            const int vr1 = (kf * 8 + tig + 4) * 72;
            #pragma unroll
            for (int nf = 0; nf < 8; nf++) {
                int n = nf * 8 + grp;
                uint32_t b0h = __float_as_uint(Vh[vr0 + n]);
                uint32_t b1h = __float_as_uint(Vh[vr1 + n]);
                uint32_t b0l = __float_as_uint(Vl[vr0 + n]);
                uint32_t b1l = __float_as_uint(Vl[vr1 + n]);
                mma_tf32_b(oacc[nf], ah, b0h, b1h);
                mma_tf32_b(oacc[nf], ah, b0l, b1l);
                mma_tf32_b(oacc[nf], al, b0h, b1h);
            }
        }
    }

    const float inv0 = 1.0f / l0, inv1 = 1.0f / l1;
    const size_t ob0 = (tokbase + row0g) * DMODEL + hh * 64;
    const size_t ob1 = (tokbase + row1g) * DMODEL + hh * 64;
    #pragma unroll
    for (int nf = 0; nf < 8; nf++) {
        int cc = nf * 8 + 2 * tig;
        o[ob0 + cc]     = rtf32(oacc[nf][0] * inv0);
        o[ob0 + cc + 1] = rtf32(oacc[nf][1] * inv0);
        o[ob1 + cc]     = rtf32(oacc[nf][2] * inv1);
        o[ob1 + cc + 1] = rtf32(oacc[nf][3] * inv1);
    }
}

// ---------------------------------------------------------------------------
// Host orchestration (graph-capturable: kernel launches only)
// ---------------------------------------------------------------------------
extern "C" void kernel_launch(void* const* d_in, const int* in_sizes, int n_in,
                              void* d_out, int out_size) {
    const int*   idx   = (const int*)d_in[0];
    const float* wte   = (const float*)d_in[1];
    const float* wpe   = (const float*)d_in[2];
    const float* ln1_w = (const float*)d_in[3];
    const float* ln1_b = (const float*)d_in[4];
    const float* Wqkv  = (const float*)d_in[5];
    const float* bqkv  = (const float*)d_in[6];
    const float* Wproj = (const float*)d_in[7];
    const float* bproj = (const float*)d_in[8];
    const float* ln2_w = (const float*)d_in[9];
    const float* ln2_b = (const float*)d_in[10];
    const float* Wfc   = (const float*)d_in[11];
    const float* bfc   = (const float*)d_in[12];
    const float* Wfc2  = (const float*)d_in[13];
    const float* bfc2  = (const float*)d_in[14];
    const float* lnf_w = (const float*)d_in[15];
    const float* lnf_b = (const float*)d_in[16];
    float* out = (float*)d_out;

    float *x, *h, *qkv, *o, *ff, *w;
    cudaGetSymbolAddress((void**)&x,   g_x);
    cudaGetSymbolAddress((void**)&h,   g_h);
    cudaGetSymbolAddress((void**)&qkv, g_qkv);
    cudaGetSymbolAddress((void**)&o,   g_o);
    cudaGetSymbolAddress((void**)&ff,  g_ff);
    cudaGetSymbolAddress((void**)&w,   g_w);

    cudaFuncSetAttribute(attn_mma_kernel,
                         cudaFuncAttributeMaxDynamicSharedMemorySize, ATTN_SMEM);
    cudaFuncSetAttribute(wgemm_kernel<false, EPI_QKV>,
                         cudaFuncAttributeMaxDynamicSharedMemorySize, WGEMM_SMEM);
    cudaFuncSetAttribute(wgemm_kernel<false, EPI_GELU>,
                         cudaFuncAttributeMaxDynamicSharedMemorySize, WGEMM_SMEM);
    cudaFuncSetAttribute(wgemm_kernel<true, EPI_NONE>,
                         cudaFuncAttributeMaxDynamicSharedMemorySize, WGEMM_SMEM);

    // Pre-round all weights into scratch (tf32, rna)
    rcopy_kernel<<<592, 256>>>(Wqkv,  w + WOFF_QKV,  NLAYER * DMODEL * 3 * DMODEL / 4);
    rcopy_kernel<<<592, 256>>>(Wproj, w + WOFF_PROJ, NLAYER * DMODEL * DMODEL / 4);
    rcopy_kernel<<<592, 256>>>(Wfc,   w + WOFF_FC,   NLAYER * DMODEL * FFDIM / 4);
    rcopy_kernel<<<592, 256>>>(Wfc2,  w + WOFF_FC2,  NLAYER * FFDIM * DMODEL / 4);
    rcopy_kernel<<<1184, 256>>>(wte,  w + WOFF_WTE,  VOCAB * DMODEL / 4);

    embed_kernel<<<(NTOK * DMODEL) / 256, 256>>>(idx, wte, wpe, x);

    for (int l = 0; l < NLAYER; l++) {
        const float* wq  = w + WOFF_QKV  + (size_t)l * DMODEL * 3 * DMODEL;
        const float* bq  = bqkv  + (size_t)l * 3 * DMODEL;
        const float* wp  = w + WOFF_PROJ + (size_t)l * DMODEL * DMODEL;
        const float* bp  = bproj + (size_t)l * DMODEL;
        const float* wf1 = w + WOFF_FC   + (size_t)l * DMODEL * FFDIM;
        const float* bf1 = bfc   + (size_t)l * FFDIM;
        const float* wf2 = w + WOFF_FC2  + (size_t)l * FFDIM * DMODEL;
        const float* bf2 = bfc2  + (size_t)l * DMODEL;

        ln_kernel<<<NTOK, 256>>>(x, ln1_w + l * DMODEL, ln1_b + l * DMODEL, h);

        wgemm_kernel<false, EPI_QKV><<<dim3(NTOK / 128, (3 * DMODEL) / 256), 256, WGEMM_SMEM>>>(
            h, wq, bq, nullptr, qkv, NTOK, 3 * DMODEL, DMODEL);

        attn_mma_kernel<<<dim3(SEQ / 64, NHEAD, NTOK / SEQ), 128, ATTN_SMEM>>>(qkv, o);

        mma_gemm_kernel<EPI_RES><<<dim3(NTOK / 128, DMODEL / 128), 256>>>(
            o, wp, bp, x, x, NTOK, DMODEL, DMODEL);

        ln_kernel<<<NTOK, 256>>>(x, ln2_w + l * DMODEL, ln2_b + l * DMODEL, h);

        wgemm_kernel<false, EPI_GELU><<<dim3(NTOK / 128, FFDIM / 256), 256, WGEMM_SMEM>>>(
            h, wf1, bf1, nullptr, ff, NTOK, FFDIM, DMODEL);

        mma_gemm_kernel<EPI_RES><<<dim3(NTOK / 128, DMODEL / 128), 256>>>(
            ff, wf2, bf2, x, x, NTOK, DMODEL, FFDIM);
    }

    ln_kernel<<<NTOK, 256>>>(x, lnf_w, lnf_b, h);

    // logits = h @ wte_rounded^T  [4096, 50257]
    wgemm_kernel<true, EPI_NONE><<<dim3(NTOK / 128, (VOCAB + 255) / 256), 256, WGEMM_SMEM>>>(
        h, w + WOFF_WTE, nullptr, nullptr, out, NTOK, VOCAB, DMODEL);
}

// round 16
// speedup vs baseline: 1.0403x; 1.0403x over previous
#include <cuda_runtime.h>
#include <math.h>
#include <cstdint>

// ---------------------------------------------------------------------------
// GPT forward. GEMMs + attention via warp-level tf32 mma.sync (sm_80 PTX --
// compiles on plain sm_103 target; tcgen05 rejected by this harness's ptxas).
// R16 (base = 3623us R13 kernel):
//   1) attention PV split 3->2 terms (PhVh+PhVl; P tf32-rounded, V exact)
//   2) scale 1/8 folded into q at QKV epilogue (power of two: bit-identical)
// B=2, S=2048 (4096 tokens), D=512, H=8, HD=64, FF=2048, L=4, V=50257.
// ---------------------------------------------------------------------------

#define NTOK   4096
#define DMODEL 512
#define NLAYER 4
#define NHEAD  8
#define HDIM   64
#define FFDIM  2048
#define SEQ    2048
#define VOCAB  50257

__device__ float g_x[NTOK * DMODEL];
__device__ float g_h[NTOK * DMODEL];
__device__ float g_qkv[NTOK * 3 * DMODEL];
__device__ float g_o[NTOK * DMODEL];
__device__ float g_ff[NTOK * FFDIM];
// Pre-rounded (tf32) weights scratch: Wqkv | Wproj | Wfc | Wfc2 | wte
#define WOFF_QKV  0
#define WOFF_PROJ 3145728
#define WOFF_FC   4194304
#define WOFF_FC2  8388608
#define WOFF_WTE  12582912
#define WTOTAL    38314496
__device__ float g_w[WTOTAL];

// ---------------------------------------------------------------------------
// tf32 / cp.async helpers
// ---------------------------------------------------------------------------
__device__ __forceinline__ float rtf32(float x) {
    uint32_t u;
    asm("cvt.rna.tf32.f32 %0, %1;" : "=r"(u) : "f"(x));
    return __uint_as_float(u);
}

__device__ __forceinline__ float4 rtf32x4(float4 v) {
    uint32_t a, b, c, d;
    asm("cvt.rna.tf32.f32 %0, %1;" : "=r"(a) : "f"(v.x));
    asm("cvt.rna.tf32.f32 %0, %1;" : "=r"(b) : "f"(v.y));
    asm("cvt.rna.tf32.f32 %0, %1;" : "=r"(c) : "f"(v.z));
    asm("cvt.rna.tf32.f32 %0, %1;" : "=r"(d) : "f"(v.w));
    v.x = __uint_as_float(a); v.y = __uint_as_float(b);
    v.z = __uint_as_float(c); v.w = __uint_as_float(d);
    return v;
}

__device__ __forceinline__ void mma_tf32(float* d, const uint32_t* a,
                                         const uint32_t* b) {
    asm volatile(
        "mma.sync.aligned.m16n8k8.row.col.f32.tf32.tf32.f32 "
        "{%0,%1,%2,%3}, {%4,%5,%6,%7}, {%8,%9}, {%0,%1,%2,%3};"
        : "+f"(d[0]), "+f"(d[1]), "+f"(d[2]), "+f"(d[3])
        : "r"(a[0]), "r"(a[1]), "r"(a[2]), "r"(a[3]),
          "r"(b[0]), "r"(b[1]));
}

__device__ __forceinline__ void mma_tf32_b(float* d, const uint32_t* a,
                                           uint32_t b0, uint32_t b1) {
    asm volatile(
        "mma.sync.aligned.m16n8k8.row.col.f32.tf32.tf32.f32 "
        "{%0,%1,%2,%3}, {%4,%5,%6,%7}, {%8,%9}, {%0,%1,%2,%3};"
        : "+f"(d[0]), "+f"(d[1]), "+f"(d[2]), "+f"(d[3])
        : "r"(a[0]), "r"(a[1]), "r"(a[2]), "r"(a[3]),
          "r"(b0), "r"(b1));
}

__device__ __forceinline__ uint32_t cvsm(const void* p) {
    return (uint32_t)__cvta_generic_to_shared(p);
}
#define CP_A16(dst, src) \
    asm volatile("cp.async.ca.shared.global [%0], [%1], 16;" \
                 :: "r"(dst), "l"(src))
#define CP_A16Z(dst, src, sb) \
    asm volatile("cp.async.ca.shared.global [%0], [%1], 16, %2;" \
                 :: "r"(dst), "l"(src), "r"(sb))
#define CP_COMMIT() asm volatile("cp.async.commit_group;")
#define CP_WAIT(n)  asm volatile("cp.async.wait_group %0;" :: "n"(n))

// ---------------------------------------------------------------------------
// Pre-round copy: dst[i] = tf32(src[i]), float4 grid-stride
// ---------------------------------------------------------------------------
__global__ void rcopy_kernel(const float* __restrict__ src,
                             float* __restrict__ dst, int n4) {
    int i = blockIdx.x * 256 + threadIdx.x;
    int stride = gridDim.x * 256;
    for (; i < n4; i += stride) {
        float4 v = *(const float4*)(src + (size_t)i * 4);
        *(float4*)(dst + (size_t)i * 4) = rtf32x4(v);
    }
}

// ---------------------------------------------------------------------------
// Embedding
// ---------------------------------------------------------------------------
__global__ void embed_kernel(const int* __restrict__ idx,
                             const float* __restrict__ wte,
                             const float* __restrict__ wpe,
                             float* __restrict__ x) {
    int i = blockIdx.x * 256 + threadIdx.x;
    int tok = i >> 9;
    int d   = i & 511;
    int s   = tok & (SEQ - 1);
    x[i] = wte[(size_t)idx[tok] * DMODEL + d] + wpe[s * DMODEL + d];
}

// ---------------------------------------------------------------------------
// LayerNorm over last dim (512); output tf32-rounded (consumed only as GEMM A)
// ---------------------------------------------------------------------------
__global__ void ln_kernel(const float* __restrict__ x,
                          const float* __restrict__ w,
                          const float* __restrict__ b,
                          float* __restrict__ out) {
    int row = blockIdx.x;
    int tid = threadIdx.x;
    const float* xr = x + (size_t)row * DMODEL;
    float v0 = xr[tid];
    float v1 = xr[tid + 256];
    float s  = v0 + v1;
    float sq = v0 * v0 + v1 * v1;
    #pragma unroll
    for (int off = 16; off >= 1; off >>= 1) {
        s  += __shfl_xor_sync(0xffffffffu, s,  off);
        sq += __shfl_xor_sync(0xffffffffu, sq, off);
    }
    __shared__ float ss[8], ssq[8];
    int warp = tid >> 5, lane = tid & 31;
    if (lane == 0) { ss[warp] = s; ssq[warp] = sq; }
    __syncthreads();
    float ts = 0.f, tq = 0.f;
    #pragma unroll
    for (int wI = 0; wI < 8; wI++) { ts += ss[wI]; tq += ssq[wI]; }
    float mean = ts * (1.0f / DMODEL);
    float var  = tq * (1.0f / DMODEL) - mean * mean;
    float rstd = rsqrtf(var + 1e-5f);
    float* outr = out + (size_t)row * DMODEL;
    outr[tid]       = rtf32((v0 - mean) * rstd * w[tid]       + b[tid]);
    outr[tid + 256] = rtf32((v1 - mean) * rstd * w[tid + 256] + b[tid + 256]);
}

#define EPI_BIAS 0
#define EPI_GELU 1
#define EPI_RES  2
#define EPI_NONE 3
#define EPI_QKV  4

// ---------------------------------------------------------------------------
// WIDE tf32 GEMM: CTA 128x256, 8 warps (2m x 4n) at 64x64 each, K chunk 32,
// cp.async double-buffered (R13 two-sync structure -- best measured).
//   TRANSB=false: B [K,N] row-major, N % 256 == 0.  (QKV, FC1)
//   TRANSB=true : B [N,K] row-major, N guarded.     (lm_head)
// EPI_GELU output tf32-rounded (feeds FC2 A).
// EPI_QKV: q cols (<512) rounded AND pre-scaled by 1/8 (exact, bit-identical
// to scaling S later); k cols (512..1023) rounded; v cols raw.
// ---------------------------------------------------------------------------
#define WGEMM_SMEM 110592

template<bool TRANSB, int EPI>
__global__ __launch_bounds__(256)
void wgemm_kernel(const float* __restrict__ A, const float* __restrict__ B,
                  const float* __restrict__ bias, const float* __restrict__ R,
                  float* __restrict__ C, int M, int N, int K) {
    extern __shared__ float wsm[];
    float* const As0 = wsm;
    float* const As1 = wsm + 4608;
    float* const Bs0 = wsm + 9216;
    float* const Bs1 = wsm + 18432;

    const int tid  = threadIdx.x;
    const int lane = tid & 31;
    const int warp = tid >> 5;
    const int wm   = warp & 1;
    const int wn   = warp >> 1;
    const int grp  = lane >> 2;
    const int tig  = lane & 3;
    const int m0   = blockIdx.x * 128;
    const int n0   = blockIdx.y * 256;

    float acc[4][8][4];
    #pragma unroll
    for (int i = 0; i < 4; i++)
        #pragma unroll
        for (int j = 0; j < 8; j++)
            #pragma unroll
            for (int r = 0; r < 4; r++) acc[i][j][r] = 0.f;

    const int nchunk = K >> 5;

    auto stage = [&](int ch, float* As, float* Bs) {
        {
            const int row = tid >> 1;
            const int f4b = (tid & 1) * 4;
            const float* g = A + (size_t)(m0 + row) * K + ch * 32 + f4b * 4;
            uint32_t s = cvsm(&As[row * 36 + f4b * 4]);
            #pragma unroll
            for (int u = 0; u < 4; u++)
                CP_A16(s + u * 16, g + u * 4);
        }
        if (!TRANSB) {
            const int n4  = tid & 31;
            const int kr0 = tid >> 5;
            #pragma unroll
            for (int u = 0; u < 4; u++) {
                int kr = kr0 + u * 8;
                const float* g = B + (size_t)(ch * 32 + kr) * N + n0 + n4 * 4;
                uint32_t s = cvsm(&Bs[kr * 264 + n4 * 4]);
                CP_A16(s, g);
                CP_A16(s + 512, g + 128);
            }
        } else {
            #pragma unroll
            for (int h = 0; h < 2; h++) {
                int nr = (tid >> 1) + h * 128;
                int gn = n0 + nr;
                uint32_t sb  = (gn < N) ? 16u : 0u;
                int      gnc = (gn < N) ? gn : 0;
                const int f4b = (tid & 1) * 4;
                const float* g = B + (size_t)gnc * K + ch * 32 + f4b * 4;
                uint32_t s = cvsm(&Bs[nr * 36 + f4b * 4]);
                #pragma unroll
                for (int u = 0; u < 4; u++)
                    CP_A16Z(s + u * 16, g + u * 4, sb);
            }
        }
    };

    stage(0, As0, Bs0);
    CP_COMMIT();

    #pragma unroll 1
    for (int ch = 0; ch < nchunk; ch++) {
        const int b = ch & 1;
        float* As = b ? As1 : As0;
        float* Bs = b ? Bs1 : Bs0;
        __syncthreads();
        if (ch + 1 < nchunk) {
            stage(ch + 1, b ? As0 : As1, b ? Bs0 : Bs1);
            CP_COMMIT();
            CP_WAIT(1);
        } else {
            CP_WAIT(0);
        }
        __syncthreads();

        #pragma unroll
        for (int ks = 0; ks < 4; ks++) {
            const int c = ks * 8 + tig;
            uint32_t af[4][4];
            #pragma unroll
            for (int mf = 0; mf < 4; mf++) {
                int r = wm * 64 + mf * 16 + grp;
                af[mf][0] = __float_as_uint(As[r * 36 + c]);
                af[mf][1] = __float_as_uint(As[(r + 8) * 36 + c]);
                af[mf][2] = __float_as_uint(As[r * 36 + c + 4]);
                af[mf][3] = __float_as_uint(As[(r + 8) * 36 + c + 4]);
            }
            uint32_t bf[8][2];
            #pragma unroll
            for (int nf = 0; nf < 8; nf++) {
                int n = wn * 64 + nf * 8 + grp;
                if (!TRANSB) {
                    bf[nf][0] = __float_as_uint(Bs[c * 264 + n]);
                    bf[nf][1] = __float_as_uint(Bs[(c + 4) * 264 + n]);
                } else {
                    bf[nf][0] = __float_as_uint(Bs[n * 36 + c]);
                    bf[nf][1] = __float_as_uint(Bs[n * 36 + c + 4]);
                }
            }
            #pragma unroll
            for (int mf = 0; mf < 4; mf++)
                #pragma unroll
                for (int nf = 0; nf < 8; nf++)
                    mma_tf32(acc[mf][nf], af[mf], bf[nf]);
        }
    }

    #pragma unroll
    for (int mf = 0; mf < 4; mf++) {
        #pragma unroll
        for (int half = 0; half < 2; half++) {
            int row = m0 + wm * 64 + mf * 16 + grp + half * 8;
            size_t ro = (size_t)row * N;
            #pragma unroll
            for (int nf = 0; nf < 8; nf++) {
                int col = n0 + wn * 64 + nf * 8 + tig * 2;
                float v0 = acc[mf][nf][half * 2 + 0];
                float v1 = acc[mf][nf][half * 2 + 1];
                if (EPI != EPI_NONE) { v0 += bias[col]; v1 += bias[col + 1]; }
                if (EPI == EPI_QKV) {
                    if (col < 512) {           // q: round + fold 1/8 (exact)
                        v0 = rtf32(v0) * 0.125f;
                        v1 = rtf32(v1) * 0.125f;
                    } else if (col < 1024) {   // k: round
                        v0 = rtf32(v0);
                        v1 = rtf32(v1);
                    }
                }
                if (EPI == EPI_GELU) {
                    v0 = rtf32(0.5f * v0 * (1.0f + erff(v0 * 0.70710678118654752f)));
                    v1 = rtf32(0.5f * v1 * (1.0f + erff(v1 * 0.70710678118654752f)));
                }
                if (EPI == EPI_RES) { v0 += R[ro + col]; v1 += R[ro + col + 1]; }
                if (!TRANSB) {
                    C[ro + col]     = v0;
                    C[ro + col + 1] = v1;
                } else {
                    if (col < N)     C[ro + col]     = v0;
                    if (col + 1 < N) C[ro + col + 1] = v1;
                }
            }
        }
    }
}

// ---------------------------------------------------------------------------
// NARROW tf32 GEMM: CTA 128x128, N=512 GEMMs. Operands pre-rounded.
// ---------------------------------------------------------------------------
template<int EPI>
__global__ __launch_bounds__(256)
void mma_gemm_kernel(const float* __restrict__ A, const float* __restrict__ B,
                     const float* __restrict__ bias, const float* __restrict__ R,
                     float* __restrict__ C, int M, int N, int K) {
    __shared__ float As[32][136];
    __shared__ float Bs[32][136];

    const int tid  = threadIdx.x;
    const int lane = tid & 31;
    const int wid  = tid >> 5;
    const int wm   = wid & 1;
    const int wn   = wid >> 1;
    const int m0   = blockIdx.x * 128;
    const int n0   = blockIdx.y * 128;

    const int tig  = lane & 3;
    const int grp  = lane >> 2;

    float acc[4][4][4];
    #pragma unroll
    for (int i = 0; i < 4; i++)
        #pragma unroll
        for (int j = 0; j < 4; j++)
            #pragma unroll
            for (int r = 0; r < 4; r++) acc[i][j][r] = 0.f;

    const int st_r  = tid >> 1;
    const int st_k0 = (tid & 1) * 16;
    const int bq_n  = (tid & 31) * 4;
    const int bq_k  = tid >> 5;

    const int nchunk = K >> 5;

    float4 pa[4], pb[4];

    {
        const float* Ap = A + (size_t)(m0 + st_r) * K + st_k0;
        #pragma unroll
        for (int u = 0; u < 4; u++)
            pa[u] = *(const float4*)(Ap + u * 4);
        #pragma unroll
        for (int u = 0; u < 4; u++)
            pb[u] = *(const float4*)(B + (size_t)(u * 8 + bq_k) * N + n0 + bq_n);
    }

    #pragma unroll 1
    for (int ch = 0; ch < nchunk; ch++) {
        __syncthreads();
        #pragma unroll
        for (int u = 0; u < 4; u++) {
            float4 av = pa[u];
            int k = st_k0 + u * 4;
            As[k + 0][st_r] = av.x;
            As[k + 1][st_r] = av.y;
            As[k + 2][st_r] = av.z;
            As[k + 3][st_r] = av.w;
            *(float4*)&Bs[u * 8 + bq_k][bq_n] = pb[u];
        }
        __syncthreads();

        if (ch + 1 < nchunk) {
            const int k0 = (ch + 1) * 32;
            const float* Ap = A + (size_t)(m0 + st_r) * K + k0 + st_k0;
            #pragma unroll
            for (int u = 0; u < 4; u++)
                pa[u] = *(const float4*)(Ap + u * 4);
            #pragma unroll
            for (int u = 0; u < 4; u++)
                pb[u] = *(const float4*)(B + (size_t)(k0 + u * 8 + bq_k) * N + n0 + bq_n);
        }

        #pragma unroll
        for (int ks = 0; ks < 4; ks++) {
            const int c = ks * 8 + tig;
            uint32_t af[4][4];
            #pragma unroll
            for (int mf = 0; mf < 4; mf++) {
                int r = wm * 64 + mf * 16 + grp;
                af[mf][0] = __float_as_uint(As[c][r]);
                af[mf][1] = __float_as_uint(As[c][r + 8]);
                af[mf][2] = __float_as_uint(As[c + 4][r]);
                af[mf][3] = __float_as_uint(As[c + 4][r + 8]);
            }
            uint32_t bf[4][2];
            #pragma unroll
            for (int nf = 0; nf < 4; nf++) {
                int n = wn * 32 + nf * 8 + grp;
                bf[nf][0] = __float_as_uint(Bs[c][n]);
                bf[nf][1] = __float_as_uint(Bs[c + 4][n]);
            }
            #pragma unroll
            for (int mf = 0; mf < 4; mf++)
                #pragma unroll
                for (int nf = 0; nf < 4; nf++)
                    mma_tf32(acc[mf][nf], af[mf], bf[nf]);
        }
    }

    #pragma unroll
    for (int mf = 0; mf < 4; mf++) {
        #pragma unroll
        for (int half = 0; half < 2; half++) {
            int row = m0 + wm * 64 + mf * 16 + grp + half * 8;
            size_t ro = (size_t)row * N;
            #pragma unroll
            for (int nf = 0; nf < 4; nf++) {
                int col = n0 + wn * 32 + nf * 8 + tig * 2;
                float v0 = acc[mf][nf][half * 2 + 0];
                float v1 = acc[mf][nf][half * 2 + 1];
                v0 += bias[col]; v1 += bias[col + 1];
                if (EPI == EPI_RES) { v0 += R[ro + col]; v1 += R[ro + col + 1]; }
                C[ro + col]     = v0;
                C[ro + col + 1] = v1;
            }
        }
    }
}

// ---------------------------------------------------------------------------
// Causal flash attention via tf32 mma.sync.
// CTA = 64 q-rows x head x batch; 128 threads = 4 warps.
// q arrives pre-rounded AND pre-scaled by 1/8; k pre-rounded (QKV epilogue).
// PV: 2-term split PhVh + PhVl (P tf32-rounded once; V kept to ~tf32^2).
// Smem 71680 B -> up to 3 CTAs/SM.
// ---------------------------------------------------------------------------
#define ATTN_SMEM 71680   // 17920 floats

__global__ __launch_bounds__(128)
void attn_mma_kernel(const float* __restrict__ qkv, float* __restrict__ o) {
    extern __shared__ float sm[];
    float* Ks = sm;              // [64][68]
    float* Vh = sm + 4352;       // [64][72]
    float* Vl = sm + 8960;       // [64][72]
    float* Ph = sm + 13568;      // [64][68]

    const int tid  = threadIdx.x;
    const int lane = tid & 31;
    const int warp = tid >> 5;
    const int grp  = lane >> 2;
    const int tig  = lane & 3;
    const int qb = blockIdx.x, hh = blockIdx.y, bb = blockIdx.z;
    const int q0 = qb * 64;
    const size_t tokbase = (size_t)bb * SEQ;

    #pragma unroll
    for (int u = 0; u < 8; u++) {
        int idx = u * 128 + tid;
        int r = idx >> 4;
        int c = (idx & 15) << 2;
        const float* src = qkv + (tokbase + q0 + r) * 1536 + hh * 64 + c;
        *(float4*)&Ks[r * 68 + c] = *(const float4*)src;
    }
    __syncthreads();

    // Q fragments: already tf32 * 1/8 (from QKV epilogue)
    uint32_t qa[8][4];
    {
        const int r0 = (warp * 16 + grp) * 68;
        const int r1 = r0 + 8 * 68;
        #pragma unroll
        for (int kf = 0; kf < 8; kf++) {
            int c = kf * 8 + tig;
            qa[kf][0] = __float_as_uint(Ks[r0 + c]);
            qa[kf][1] = __float_as_uint(Ks[r1 + c]);
            qa[kf][2] = __float_as_uint(Ks[r0 + c + 4]);
            qa[kf][3] = __float_as_uint(Ks[r1 + c + 4]);
        }
    }

    float m0 = -1e30f, m1 = -1e30f, l0 = 0.f, l1 = 0.f;
    float oacc[8][4];
    #pragma unroll
    for (int nf = 0; nf < 8; nf++)
        #pragma unroll
        for (int c = 0; c < 4; c++) oacc[nf][c] = 0.f;

    const int prow0 = (warp * 16 + grp) * 68;
    const int prow1 = prow0 + 8 * 68;
    const int row0g = q0 + warp * 16 + grp;
    const int row1g = row0g + 8;

    #pragma unroll 1
    for (int kb = 0; kb <= qb; kb++) {
        const int k0 = kb * 64;
        __syncthreads();
        // K already tf32: plain copy. V: hi/lo split.
        #pragma unroll
        for (int u = 0; u < 8; u++) {
            int idx = u * 128 + tid;
            int r = idx >> 4;
            int c = (idx & 15) << 2;
            const float* kp = qkv + (tokbase + k0 + r) * 1536 + 512 + hh * 64 + c;
            *(float4*)&Ks[r * 68 + c] = *(const float4*)kp;
            const float* vp = qkv + (tokbase + k0 + r) * 1536 + 1024 + hh * 64 + c;
            float4 v  = *(const float4*)vp;
            float4 vh = rtf32x4(v);
            float4 vl;
            vl.x = v.x - vh.x; vl.y = v.y - vh.y;
            vl.z = v.z - vh.z; vl.w = v.w - vh.w;
            vl = rtf32x4(vl);
            *(float4*)&Vh[r * 72 + c] = vh;
            *(float4*)&Vl[r * 72 + c] = vl;
        }
        __syncthreads();

        // S = (q/8) @ K^T  -- scale already folded, exact
        float sacc[8][4];
        #pragma unroll
        for (int nf = 0; nf < 8; nf++) {
            #pragma unroll
            for (int c = 0; c < 4; c++) sacc[nf][c] = 0.f;
            const int kb_row = (nf * 8 + grp) * 68;
            #pragma unroll
            for (int kf = 0; kf < 8; kf++) {
                uint32_t b0 = __float_as_uint(Ks[kb_row + kf * 8 + tig]);
                uint32_t b1 = __float_as_uint(Ks[kb_row + kf * 8 + tig + 4]);
                mma_tf32_b(sacc[nf], qa[kf], b0, b1);
            }
        }

        // causal mask (values already scaled)
        #pragma unroll
        for (int nf = 0; nf < 8; nf++) {
            int colb = k0 + nf * 8 + 2 * tig;
            if (colb     > row0g) sacc[nf][0] = -1e30f;
            if (colb + 1 > row0g) sacc[nf][1] = -1e30f;
            if (colb     > row1g) sacc[nf][2] = -1e30f;
            if (colb + 1 > row1g) sacc[nf][3] = -1e30f;
        }

        float rm0 = -1e30f, rm1 = -1e30f;
        #pragma unroll
        for (int nf = 0; nf < 8; nf++) {
            rm0 = fmaxf(rm0, fmaxf(sacc[nf][0], sacc[nf][1]));
            rm1 = fmaxf(rm1, fmaxf(sacc[nf][2], sacc[nf][3]));
        }
        rm0 = fmaxf(rm0, __shfl_xor_sync(0xffffffffu, rm0, 1));
        rm0 = fmaxf(rm0, __shfl_xor_sync(0xffffffffu, rm0, 2));
        rm1 = fmaxf(rm1, __shfl_xor_sync(0xffffffffu, rm1, 1));
        rm1 = fmaxf(rm1, __shfl_xor_sync(0xffffffffu, rm1, 2));
        float nm0 = fmaxf(m0, rm0), nm1 = fmaxf(m1, rm1);
        float corr0 = __expf(m0 - nm0), corr1 = __expf(m1 - nm1);
        float rs0 = 0.f, rs1 = 0.f;
        #pragma unroll
        for (int nf = 0; nf < 8; nf++) {
            float p0 = __expf(sacc[nf][0] - nm0);
            float p1 = __expf(sacc[nf][1] - nm0);
            float p2 = __expf(sacc[nf][2] - nm1);
            float p3 = __expf(sacc[nf][3] - nm1);
            rs0 += p0 + p1; rs1 += p2 + p3;
            sacc[nf][0] = p0; sacc[nf][1] = p1;
            sacc[nf][2] = p2; sacc[nf][3] = p3;
        }
        rs0 += __shfl_xor_sync(0xffffffffu, rs0, 1);
        rs0 += __shfl_xor_sync(0xffffffffu, rs0, 2);
        rs1 += __shfl_xor_sync(0xffffffffu, rs1, 1);
        rs1 += __shfl_xor_sync(0xffffffffu, rs1, 2);
        l0 = l0 * corr0 + rs0;  m0 = nm0;
        l1 = l1 * corr1 + rs1;  m1 = nm1;
        #pragma unroll
        for (int nf = 0; nf < 8; nf++) {
            oacc[nf][0] *= corr0; oacc[nf][1] *= corr0;
            oacc[nf][2] *= corr1; oacc[nf][3] *= corr1;
        }

        // P (tf32-rounded) to warp-private smem strip
        #pragma unroll
        for (int nf = 0; nf < 8; nf++) {
            int cc = nf * 8 + 2 * tig;
            Ph[prow0 + cc]     = rtf32(sacc[nf][0]);
            Ph[prow0 + cc + 1] = rtf32(sacc[nf][1]);
            Ph[prow1 + cc]     = rtf32(sacc[nf][2]);
            Ph[prow1 + cc + 1] = rtf32(sacc[nf][3]);
        }
        __syncwarp();

        // O += P @ (Vh + Vl)  -- 2-term split
        #pragma unroll
        for (int kf = 0; kf < 8; kf++) {
            uint32_t ah[4];
            int c = kf * 8 + tig;
            ah[0] = __float_as_uint(Ph[prow0 + c]);
            ah[1] = __float_as_uint(Ph[prow1 + c]);
            ah[2] = __float_as_uint(Ph[prow0 + c + 4]);
            ah[3] = __float_as_uint(Ph[prow1 + c + 4]);
            const int vr0 = (kf * 8 + tig) * 72;
            const int vr1 = (kf * 8 + tig + 4) * 72;
            #pragma unroll
            for (int nf = 0; nf < 8; nf++) {
                int n = nf * 8 + grp;
                uint32_t b0h = __float_as_uint(Vh[vr0 + n]);
                uint32_t b1h = __float_as_uint(Vh[vr1 + n]);
                uint32_t b0l = __float_as_uint(Vl[vr0 + n]);
                uint32_t b1l = __float_as_uint(Vl[vr1 + n]);
                mma_tf32_b(oacc[nf], ah, b0h, b1h);
                mma_tf32_b(oacc[nf], ah, b0l, b1l);
            }
        }
    }

    const float inv0 = 1.0f / l0, inv1 = 1.0f / l1;
    const size_t ob0 = (tokbase + row0g) * DMODEL + hh * 64;
    const size_t ob1 = (tokbase + row1g) * DMODEL + hh * 64;
    #pragma unroll
    for (int nf = 0; nf < 8; nf++) {
        int cc = nf * 8 + 2 * tig;
        o[ob0 + cc]     = rtf32(oacc[nf][0] * inv0);
        o[ob0 + cc + 1] = rtf32(oacc[nf][1] * inv0);
        o[ob1 + cc]     = rtf32(oacc[nf][2] * inv1);
        o[ob1 + cc + 1] = rtf32(oacc[nf][3] * inv1);
    }
}

// ---------------------------------------------------------------------------
// Host orchestration (graph-capturable: kernel launches only)
// ---------------------------------------------------------------------------
extern "C" void kernel_launch(void* const* d_in, const int* in_sizes, int n_in,
                              void* d_out, int out_size) {
    const int*   idx   = (const int*)d_in[0];
    const float* wte   = (const float*)d_in[1];
    const float* wpe   = (const float*)d_in[2];
    const float* ln1_w = (const float*)d_in[3];
    const float* ln1_b = (const float*)d_in[4];
    const float* Wqkv  = (const float*)d_in[5];
    const float* bqkv  = (const float*)d_in[6];
    const float* Wproj = (const float*)d_in[7];
    const float* bproj = (const float*)d_in[8];
    const float* ln2_w = (const float*)d_in[9];
    const float* ln2_b = (const float*)d_in[10];
    const float* Wfc   = (const float*)d_in[11];
    const float* bfc   = (const float*)d_in[12];
    const float* Wfc2  = (const float*)d_in[13];
    const float* bfc2  = (const float*)d_in[14];
    const float* lnf_w = (const float*)d_in[15];
    const float* lnf_b = (const float*)d_in[16];
    float* out = (float*)d_out;

    float *x, *h, *qkv, *o, *ff, *w;
    cudaGetSymbolAddress((void**)&x,   g_x);
    cudaGetSymbolAddress((void**)&h,   g_h);
    cudaGetSymbolAddress((void**)&qkv, g_qkv);
    cudaGetSymbolAddress((void**)&o,   g_o);
    cudaGetSymbolAddress((void**)&ff,  g_ff);
    cudaGetSymbolAddress((void**)&w,   g_w);

    cudaFuncSetAttribute(attn_mma_kernel,
                         cudaFuncAttributeMaxDynamicSharedMemorySize, ATTN_SMEM);
    cudaFuncSetAttribute(wgemm_kernel<false, EPI_QKV>,
                         cudaFuncAttributeMaxDynamicSharedMemorySize, WGEMM_SMEM);
    cudaFuncSetAttribute(wgemm_kernel<false, EPI_GELU>,
                         cudaFuncAttributeMaxDynamicSharedMemorySize, WGEMM_SMEM);
    cudaFuncSetAttribute(wgemm_kernel<true, EPI_NONE>,
                         cudaFuncAttributeMaxDynamicSharedMemorySize, WGEMM_SMEM);

    // Pre-round all weights into scratch (tf32, rna)
    rcopy_kernel<<<592, 256>>>(Wqkv,  w + WOFF_QKV,  NLAYER * DMODEL * 3 * DMODEL / 4);
    rcopy_kernel<<<592, 256>>>(Wproj, w + WOFF_PROJ, NLAYER * DMODEL * DMODEL / 4);
    rcopy_kernel<<<592, 256>>>(Wfc,   w + WOFF_FC,   NLAYER * DMODEL * FFDIM / 4);
    rcopy_kernel<<<592, 256>>>(Wfc2,  w + WOFF_FC2,  NLAYER * FFDIM * DMODEL / 4);
    rcopy_kernel<<<1184, 256>>>(wte,  w + WOFF_WTE,  VOCAB * DMODEL / 4);

    embed_kernel<<<(NTOK * DMODEL) / 256, 256>>>(idx, wte, wpe, x);

    for (int l = 0; l < NLAYER; l++) {
        const float* wq  = w + WOFF_QKV  + (size_t)l * DMODEL * 3 * DMODEL;
        const float* bq  = bqkv  + (size_t)l * 3 * DMODEL;
        const float* wp  = w + WOFF_PROJ + (size_t)l * DMODEL * DMODEL;
        const float* bp  = bproj + (size_t)l * DMODEL;
        const float* wf1 = w + WOFF_FC   + (size_t)l * DMODEL * FFDIM;
        const float* bf1 = bfc   + (size_t)l * FFDIM;
        const float* wf2 = w + WOFF_FC2  + (size_t)l * FFDIM * DMODEL;
        const float* bf2 = bfc2  + (size_t)l * DMODEL;

        ln_kernel<<<NTOK, 256>>>(x, ln1_w + l * DMODEL, ln1_b + l * DMODEL, h);

        wgemm_kernel<false, EPI_QKV><<<dim3(NTOK / 128, (3 * DMODEL) / 256), 256, WGEMM_SMEM>>>(
            h, wq, bq, nullptr, qkv, NTOK, 3 * DMODEL, DMODEL);

        attn_mma_kernel<<<dim3(SEQ / 64, NHEAD, NTOK / SEQ), 128, ATTN_SMEM>>>(qkv, o);

        mma_gemm_kernel<EPI_RES><<<dim3(NTOK / 128, DMODEL / 128), 256>>>(
            o, wp, bp, x, x, NTOK, DMODEL, DMODEL);

        ln_kernel<<<NTOK, 256>>>(x, ln2_w + l * DMODEL, ln2_b + l * DMODEL, h);

        wgemm_kernel<false, EPI_GELU><<<dim3(NTOK / 128, FFDIM / 256), 256, WGEMM_SMEM>>>(
            h, wf1, bf1, nullptr, ff, NTOK, FFDIM, DMODEL);

        mma_gemm_kernel<EPI_RES><<<dim3(NTOK / 128, DMODEL / 128), 256>>>(
            ff, wf2, bf2, x, x, NTOK, DMODEL, FFDIM);
    }

    ln_kernel<<<NTOK, 256>>>(x, lnf_w, lnf_b, h);

    // logits = h @ wte_rounded^T  [4096, 50257]
    wgemm_kernel<true, EPI_NONE><<<dim3(NTOK / 128, (VOCAB + 255) / 256), 256, WGEMM_SMEM>>>(
        h, w + WOFF_WTE, nullptr, nullptr, out, NTOK, VOCAB, DMODEL);
}

// round 17
// speedup vs baseline: 1.0775x; 1.0358x over previous
#include <cuda_runtime.h>
#include <math.h>
#include <cstdint>

// ---------------------------------------------------------------------------
// GPT forward. GEMMs + attention via warp-level tf32 mma.sync (sm_80 PTX --
// compiles on plain sm_103 target; tcgen05 rejected by this harness's ptxas).
// R17 (base = 3510us R16 kernel): attention PV split 2->1 term (Ph@Vh only;
// V tf32-rounded at staging). Calibrated error model: +~5e-5 in quadrature.
// B=2, S=2048 (4096 tokens), D=512, H=8, HD=64, FF=2048, L=4, V=50257.
// ---------------------------------------------------------------------------

#define NTOK   4096
#define DMODEL 512
#define NLAYER 4
#define NHEAD  8
#define HDIM   64
#define FFDIM  2048
#define SEQ    2048
#define VOCAB  50257

__device__ float g_x[NTOK * DMODEL];
__device__ float g_h[NTOK * DMODEL];
__device__ float g_qkv[NTOK * 3 * DMODEL];
__device__ float g_o[NTOK * DMODEL];
__device__ float g_ff[NTOK * FFDIM];
// Pre-rounded (tf32) weights scratch: Wqkv | Wproj | Wfc | Wfc2 | wte
#define WOFF_QKV  0
#define WOFF_PROJ 3145728
#define WOFF_FC   4194304
#define WOFF_FC2  8388608
#define WOFF_WTE  12582912
#define WTOTAL    38314496
__device__ float g_w[WTOTAL];

// ---------------------------------------------------------------------------
// tf32 / cp.async helpers
// ---------------------------------------------------------------------------
__device__ __forceinline__ float rtf32(float x) {
    uint32_t u;
    asm("cvt.rna.tf32.f32 %0, %1;" : "=r"(u) : "f"(x));
    return __uint_as_float(u);
}

__device__ __forceinline__ float4 rtf32x4(float4 v) {
    uint32_t a, b, c, d;
    asm("cvt.rna.tf32.f32 %0, %1;" : "=r"(a) : "f"(v.x));
    asm("cvt.rna.tf32.f32 %0, %1;" : "=r"(b) : "f"(v.y));
    asm("cvt.rna.tf32.f32 %0, %1;" : "=r"(c) : "f"(v.z));
    asm("cvt.rna.tf32.f32 %0, %1;" : "=r"(d) : "f"(v.w));
    v.x = __uint_as_float(a); v.y = __uint_as_float(b);
    v.z = __uint_as_float(c); v.w = __uint_as_float(d);
    return v;
}

__device__ __forceinline__ void mma_tf32(float* d, const uint32_t* a,
                                         const uint32_t* b) {
    asm volatile(
        "mma.sync.aligned.m16n8k8.row.col.f32.tf32.tf32.f32 "
        "{%0,%1,%2,%3}, {%4,%5,%6,%7}, {%8,%9}, {%0,%1,%2,%3};"
        : "+f"(d[0]), "+f"(d[1]), "+f"(d[2]), "+f"(d[3])
        : "r"(a[0]), "r"(a[1]), "r"(a[2]), "r"(a[3]),
          "r"(b[0]), "r"(b[1]));
}

__device__ __forceinline__ void mma_tf32_b(float* d, const uint32_t* a,
                                           uint32_t b0, uint32_t b1) {
    asm volatile(
        "mma.sync.aligned.m16n8k8.row.col.f32.tf32.tf32.f32 "
        "{%0,%1,%2,%3}, {%4,%5,%6,%7}, {%8,%9}, {%0,%1,%2,%3};"
        : "+f"(d[0]), "+f"(d[1]), "+f"(d[2]), "+f"(d[3])
        : "r"(a[0]), "r"(a[1]), "r"(a[2]), "r"(a[3]),
          "r"(b0), "r"(b1));
}

__device__ __forceinline__ uint32_t cvsm(const void* p) {
    return (uint32_t)__cvta_generic_to_shared(p);
}
#define CP_A16(dst, src) \
    asm volatile("cp.async.ca.shared.global [%0], [%1], 16;" \
                 :: "r"(dst), "l"(src))
#define CP_A16Z(dst, src, sb) \
    asm volatile("cp.async.ca.shared.global [%0], [%1], 16, %2;" \
                 :: "r"(dst), "l"(src), "r"(sb))
#define CP_COMMIT() asm volatile("cp.async.commit_group;")
#define CP_WAIT(n)  asm volatile("cp.async.wait_group %0;" :: "n"(n))

// ---------------------------------------------------------------------------
// Pre-round copy: dst[i] = tf32(src[i]), float4 grid-stride
// ---------------------------------------------------------------------------
__global__ void rcopy_kernel(const float* __restrict__ src,
                             float* __restrict__ dst, int n4) {
    int i = blockIdx.x * 256 + threadIdx.x;
    int stride = gridDim.x * 256;
    for (; i < n4; i += stride) {
        float4 v = *(const float4*)(src + (size_t)i * 4);
        *(float4*)(dst + (size_t)i * 4) = rtf32x4(v);
    }
}

// ---------------------------------------------------------------------------
// Embedding
// ---------------------------------------------------------------------------
__global__ void embed_kernel(const int* __restrict__ idx,
                             const float* __restrict__ wte,
                             const float* __restrict__ wpe,
                             float* __restrict__ x) {
    int i = blockIdx.x * 256 + threadIdx.x;
    int tok = i >> 9;
    int d   = i & 511;
    int s   = tok & (SEQ - 1);
    x[i] = wte[(size_t)idx[tok] * DMODEL + d] + wpe[s * DMODEL + d];
}

// ---------------------------------------------------------------------------
// LayerNorm over last dim (512); output tf32-rounded (consumed only as GEMM A)
// ---------------------------------------------------------------------------
__global__ void ln_kernel(const float* __restrict__ x,
                          const float* __restrict__ w,
                          const float* __restrict__ b,
                          float* __restrict__ out) {
    int row = blockIdx.x;
    int tid = threadIdx.x;
    const float* xr = x + (size_t)row * DMODEL;
    float v0 = xr[tid];
    float v1 = xr[tid + 256];
    float s  = v0 + v1;
    float sq = v0 * v0 + v1 * v1;
    #pragma unroll
    for (int off = 16; off >= 1; off >>= 1) {
        s  += __shfl_xor_sync(0xffffffffu, s,  off);
        sq += __shfl_xor_sync(0xffffffffu, sq, off);
    }
    __shared__ float ss[8], ssq[8];
    int warp = tid >> 5, lane = tid & 31;
    if (lane == 0) { ss[warp] = s; ssq[warp] = sq; }
    __syncthreads();
    float ts = 0.f, tq = 0.f;
    #pragma unroll
    for (int wI = 0; wI < 8; wI++) { ts += ss[wI]; tq += ssq[wI]; }
    float mean = ts * (1.0f / DMODEL);
    float var  = tq * (1.0f / DMODEL) - mean * mean;
    float rstd = rsqrtf(var + 1e-5f);
    float* outr = out + (size_t)row * DMODEL;
    outr[tid]       = rtf32((v0 - mean) * rstd * w[tid]       + b[tid]);
    outr[tid + 256] = rtf32((v1 - mean) * rstd * w[tid + 256] + b[tid + 256]);
}

#define EPI_BIAS 0
#define EPI_GELU 1
#define EPI_RES  2
#define EPI_NONE 3
#define EPI_QKV  4

// ---------------------------------------------------------------------------
// WIDE tf32 GEMM: CTA 128x256, 8 warps (2m x 4n) at 64x64 each, K chunk 32,
// cp.async double-buffered (R13 two-sync structure -- best measured).
//   TRANSB=false: B [K,N] row-major, N % 256 == 0.  (QKV, FC1)
//   TRANSB=true : B [N,K] row-major, N guarded.     (lm_head)
// EPI_GELU output tf32-rounded (feeds FC2 A).
// EPI_QKV: q cols (<512) rounded AND pre-scaled by 1/8 (exact); k cols
// (512..1023) rounded; v cols raw.
// ---------------------------------------------------------------------------
#define WGEMM_SMEM 110592

template<bool TRANSB, int EPI>
__global__ __launch_bounds__(256)
void wgemm_kernel(const float* __restrict__ A, const float* __restrict__ B,
                  const float* __restrict__ bias, const float* __restrict__ R,
                  float* __restrict__ C, int M, int N, int K) {
    extern __shared__ float wsm[];
    float* const As0 = wsm;
    float* const As1 = wsm + 4608;
    float* const Bs0 = wsm + 9216;
    float* const Bs1 = wsm + 18432;

    const int tid  = threadIdx.x;
    const int lane = tid & 31;
    const int warp = tid >> 5;
    const int wm   = warp & 1;
    const int wn   = warp >> 1;
    const int grp  = lane >> 2;
    const int tig  = lane & 3;
    const int m0   = blockIdx.x * 128;
    const int n0   = blockIdx.y * 256;

    float acc[4][8][4];
    #pragma unroll
    for (int i = 0; i < 4; i++)
        #pragma unroll
        for (int j = 0; j < 8; j++)
            #pragma unroll
            for (int r = 0; r < 4; r++) acc[i][j][r] = 0.f;

    const int nchunk = K >> 5;

    auto stage = [&](int ch, float* As, float* Bs) {
        {
            const int row = tid >> 1;
            const int f4b = (tid & 1) * 4;
            const float* g = A + (size_t)(m0 + row) * K + ch * 32 + f4b * 4;
            uint32_t s = cvsm(&As[row * 36 + f4b * 4]);
            #pragma unroll
            for (int u = 0; u < 4; u++)
                CP_A16(s + u * 16, g + u * 4);
        }
        if (!TRANSB) {
            const int n4  = tid & 31;
            const int kr0 = tid >> 5;
            #pragma unroll
            for (int u = 0; u < 4; u++) {
                int kr = kr0 + u * 8;
                const float* g = B + (size_t)(ch * 32 + kr) * N + n0 + n4 * 4;
                uint32_t s = cvsm(&Bs[kr * 264 + n4 * 4]);
                CP_A16(s, g);
                CP_A16(s + 512, g + 128);
            }
        } else {
            #pragma unroll
            for (int h = 0; h < 2; h++) {
                int nr = (tid >> 1) + h * 128;
                int gn = n0 + nr;
                uint32_t sb  = (gn < N) ? 16u : 0u;
                int      gnc = (gn < N) ? gn : 0;
                const int f4b = (tid & 1) * 4;
                const float* g = B + (size_t)gnc * K + ch * 32 + f4b * 4;
                uint32_t s = cvsm(&Bs[nr * 36 + f4b * 4]);
                #pragma unroll
                for (int u = 0; u < 4; u++)
                    CP_A16Z(s + u * 16, g + u * 4, sb);
            }
        }
    };

    stage(0, As0, Bs0);
    CP_COMMIT();

    #pragma unroll 1
    for (int ch = 0; ch < nchunk; ch++) {
        const int b = ch & 1;
        float* As = b ? As1 : As0;
        float* Bs = b ? Bs1 : Bs0;
        __syncthreads();
        if (ch + 1 < nchunk) {
            stage(ch + 1, b ? As0 : As1, b ? Bs0 : Bs1);
            CP_COMMIT();
            CP_WAIT(1);
        } else {
            CP_WAIT(0);
        }
        __syncthreads();

        #pragma unroll
        for (int ks = 0; ks < 4; ks++) {
            const int c = ks * 8 + tig;
            uint32_t af[4][4];
            #pragma unroll
            for (int mf = 0; mf < 4; mf++) {
                int r = wm * 64 + mf * 16 + grp;
                af[mf][0] = __float_as_uint(As[r * 36 + c]);
                af[mf][1] = __float_as_uint(As[(r + 8) * 36 + c]);
                af[mf][2] = __float_as_uint(As[r * 36 + c + 4]);
                af[mf][3] = __float_as_uint(As[(r + 8) * 36 + c + 4]);
            }
            uint32_t bf[8][2];
            #pragma unroll
            for (int nf = 0; nf < 8; nf++) {
                int n = wn * 64 + nf * 8 + grp;
                if (!TRANSB) {
                    bf[nf][0] = __float_as_uint(Bs[c * 264 + n]);
                    bf[nf][1] = __float_as_uint(Bs[(c + 4) * 264 + n]);
                } else {
                    bf[nf][0] = __float_as_uint(Bs[n * 36 + c]);
                    bf[nf][1] = __float_as_uint(Bs[n * 36 + c + 4]);
                }
            }
            #pragma unroll
            for (int mf = 0; mf < 4; mf++)
                #pragma unroll
                for (int nf = 0; nf < 8; nf++)
                    mma_tf32(acc[mf][nf], af[mf], bf[nf]);
        }
    }

    #pragma unroll
    for (int mf = 0; mf < 4; mf++) {
        #pragma unroll
        for (int half = 0; half < 2; half++) {
            int row = m0 + wm * 64 + mf * 16 + grp + half * 8;
            size_t ro = (size_t)row * N;
            #pragma unroll
            for (int nf = 0; nf < 8; nf++) {
                int col = n0 + wn * 64 + nf * 8 + tig * 2;
                float v0 = acc[mf][nf][half * 2 + 0];
                float v1 = acc[mf][nf][half * 2 + 1];
                if (EPI != EPI_NONE) { v0 += bias[col]; v1 += bias[col + 1]; }
                if (EPI == EPI_QKV) {
                    if (col < 512) {           // q: round + fold 1/8 (exact)
                        v0 = rtf32(v0) * 0.125f;
                        v1 = rtf32(v1) * 0.125f;
                    } else if (col < 1024) {   // k: round
                        v0 = rtf32(v0);
                        v1 = rtf32(v1);
                    }
                }
                if (EPI == EPI_GELU) {
                    v0 = rtf32(0.5f * v0 * (1.0f + erff(v0 * 0.70710678118654752f)));
                    v1 = rtf32(0.5f * v1 * (1.0f + erff(v1 * 0.70710678118654752f)));
                }
                if (EPI == EPI_RES) { v0 += R[ro + col]; v1 += R[ro + col + 1]; }
                if (!TRANSB) {
                    C[ro + col]     = v0;
                    C[ro + col + 1] = v1;
                } else {
                    if (col < N)     C[ro + col]     = v0;
                    if (col + 1 < N) C[ro + col + 1] = v1;
                }
            }
        }
    }
}

// ---------------------------------------------------------------------------
// NARROW tf32 GEMM: CTA 128x128, N=512 GEMMs. Operands pre-rounded.
// ---------------------------------------------------------------------------
template<int EPI>
__global__ __launch_bounds__(256)
void mma_gemm_kernel(const float* __restrict__ A, const float* __restrict__ B,
                     const float* __restrict__ bias, const float* __restrict__ R,
                     float* __restrict__ C, int M, int N, int K) {
    __shared__ float As[32][136];
    __shared__ float Bs[32][136];

    const int tid  = threadIdx.x;
    const int lane = tid & 31;
    const int wid  = tid >> 5;
    const int wm   = wid & 1;
    const int wn   = wid >> 1;
    const int m0   = blockIdx.x * 128;
    const int n0   = blockIdx.y * 128;

    const int tig  = lane & 3;
    const int grp  = lane >> 2;

    float acc[4][4][4];
    #pragma unroll
    for (int i = 0; i < 4; i++)
        #pragma unroll
        for (int j = 0; j < 4; j++)
            #pragma unroll
            for (int r = 0; r < 4; r++) acc[i][j][r] = 0.f;

    const int st_r  = tid >> 1;
    const int st_k0 = (tid & 1) * 16;
    const int bq_n  = (tid & 31) * 4;
    const int bq_k  = tid >> 5;

    const int nchunk = K >> 5;

    float4 pa[4], pb[4];

    {
        const float* Ap = A + (size_t)(m0 + st_r) * K + st_k0;
        #pragma unroll
        for (int u = 0; u < 4; u++)
            pa[u] = *(const float4*)(Ap + u * 4);
        #pragma unroll
        for (int u = 0; u < 4; u++)
            pb[u] = *(const float4*)(B + (size_t)(u * 8 + bq_k) * N + n0 + bq_n);
    }

    #pragma unroll 1
    for (int ch = 0; ch < nchunk; ch++) {
        __syncthreads();
        #pragma unroll
        for (int u = 0; u < 4; u++) {
            float4 av = pa[u];
            int k = st_k0 + u * 4;
            As[k + 0][st_r] = av.x;
            As[k + 1][st_r] = av.y;
            As[k + 2][st_r] = av.z;
            As[k + 3][st_r] = av.w;
            *(float4*)&Bs[u * 8 + bq_k][bq_n] = pb[u];
        }
        __syncthreads();

        if (ch + 1 < nchunk) {
            const int k0 = (ch + 1) * 32;
            const float* Ap = A + (size_t)(m0 + st_r) * K + k0 + st_k0;
            #pragma unroll
            for (int u = 0; u < 4; u++)
                pa[u] = *(const float4*)(Ap + u * 4);
            #pragma unroll
            for (int u = 0; u < 4; u++)
                pb[u] = *(const float4*)(B + (size_t)(k0 + u * 8 + bq_k) * N + n0 + bq_n);
        }

        #pragma unroll
        for (int ks = 0; ks < 4; ks++) {
            const int c = ks * 8 + tig;
            uint32_t af[4][4];
            #pragma unroll
            for (int mf = 0; mf < 4; mf++) {
                int r = wm * 64 + mf * 16 + grp;
                af[mf][0] = __float_as_uint(As[c][r]);
                af[mf][1] = __float_as_uint(As[c][r + 8]);
                af[mf][2] = __float_as_uint(As[c + 4][r]);
                af[mf][3] = __float_as_uint(As[c + 4][r + 8]);
            }
            uint32_t bf[4][2];
            #pragma unroll
            for (int nf = 0; nf < 4; nf++) {
                int n = wn * 32 + nf * 8 + grp;
                bf[nf][0] = __float_as_uint(Bs[c][n]);
                bf[nf][1] = __float_as_uint(Bs[c + 4][n]);
            }
            #pragma unroll
            for (int mf = 0; mf < 4; mf++)
                #pragma unroll
                for (int nf = 0; nf < 4; nf++)
                    mma_tf32(acc[mf][nf], af[mf], bf[nf]);
        }
    }

    #pragma unroll
    for (int mf = 0; mf < 4; mf++) {
        #pragma unroll
        for (int half = 0; half < 2; half++) {
            int row = m0 + wm * 64 + mf * 16 + grp + half * 8;
            size_t ro = (size_t)row * N;
            #pragma unroll
            for (int nf = 0; nf < 4; nf++) {
                int col = n0 + wn * 32 + nf * 8 + tig * 2;
                float v0 = acc[mf][nf][half * 2 + 0];
                float v1 = acc[mf][nf][half * 2 + 1];
                v0 += bias[col]; v1 += bias[col + 1];
                if (EPI == EPI_RES) { v0 += R[ro + col]; v1 += R[ro + col + 1]; }
                C[ro + col]     = v0;
                C[ro + col + 1] = v1;
            }
        }
    }
}

// ---------------------------------------------------------------------------
// Causal flash attention via tf32 mma.sync.
// CTA = 64 q-rows x head x batch; 128 threads = 4 warps.
// q arrives pre-rounded AND pre-scaled by 1/8; k pre-rounded (QKV epilogue).
// PV: single term Ph@Vh (P and V both tf32-rounded; calibrated error budget).
// Smem 53248 B -> up to 4 CTAs/SM.
// ---------------------------------------------------------------------------
#define ATTN_SMEM 53248   // 13312 floats

__global__ __launch_bounds__(128)
void attn_mma_kernel(const float* __restrict__ qkv, float* __restrict__ o) {
    extern __shared__ float sm[];
    float* Ks = sm;              // [64][68]
    float* Vh = sm + 4352;       // [64][72]
    float* Ph = sm + 8960;       // [64][68]

    const int tid  = threadIdx.x;
    const int lane = tid & 31;
    const int warp = tid >> 5;
    const int grp  = lane >> 2;
    const int tig  = lane & 3;
    const int qb = blockIdx.x, hh = blockIdx.y, bb = blockIdx.z;
    const int q0 = qb * 64;
    const size_t tokbase = (size_t)bb * SEQ;

    #pragma unroll
    for (int u = 0; u < 8; u++) {
        int idx = u * 128 + tid;
        int r = idx >> 4;
        int c = (idx & 15) << 2;
        const float* src = qkv + (tokbase + q0 + r) * 1536 + hh * 64 + c;
        *(float4*)&Ks[r * 68 + c] = *(const float4*)src;
    }
    __syncthreads();

    // Q fragments: already tf32 * 1/8 (from QKV epilogue)
    uint32_t qa[8][4];
    {
        const int r0 = (warp * 16 + grp) * 68;
        const int r1 = r0 + 8 * 68;
        #pragma unroll
        for (int kf = 0; kf < 8; kf++) {
            int c = kf * 8 + tig;
            qa[kf][0] = __float_as_uint(Ks[r0 + c]);
            qa[kf][1] = __float_as_uint(Ks[r1 + c]);
            qa[kf][2] = __float_as_uint(Ks[r0 + c + 4]);
            qa[kf][3] = __float_as_uint(Ks[r1 + c + 4]);
        }
    }

    float m0 = -1e30f, m1 = -1e30f, l0 = 0.f, l1 = 0.f;
    float oacc[8][4];
    #pragma unroll
    for (int nf = 0; nf < 8; nf++)
        #pragma unroll
        for (int c = 0; c < 4; c++) oacc[nf][c] = 0.f;

    const int prow0 = (warp * 16 + grp) * 68;
    const int prow1 = prow0 + 8 * 68;
    const int row0g = q0 + warp * 16 + grp;
    const int row1g = row0g + 8;

    #pragma unroll 1
    for (int kb = 0; kb <= qb; kb++) {
        const int k0 = kb * 64;
        __syncthreads();
        // K already tf32: plain copy. V: tf32-round at staging.
        #pragma unroll
        for (int u = 0; u < 8; u++) {
            int idx = u * 128 + tid;
            int r = idx >> 4;
            int c = (idx & 15) << 2;
            const float* kp = qkv + (tokbase + k0 + r) * 1536 + 512 + hh * 64 + c;
            *(float4*)&Ks[r * 68 + c] = *(const float4*)kp;
            const float* vp = qkv + (tokbase + k0 + r) * 1536 + 1024 + hh * 64 + c;
            *(float4*)&Vh[r * 72 + c] = rtf32x4(*(const float4*)vp);
        }
        __syncthreads();

        // S = (q/8) @ K^T  -- scale already folded, exact
        float sacc[8][4];
        #pragma unroll
        for (int nf = 0; nf < 8; nf++) {
            #pragma unroll
            for (int c = 0; c < 4; c++) sacc[nf][c] = 0.f;
            const int kb_row = (nf * 8 + grp) * 68;
            #pragma unroll
            for (int kf = 0; kf < 8; kf++) {
                uint32_t b0 = __float_as_uint(Ks[kb_row + kf * 8 + tig]);
                uint32_t b1 = __float_as_uint(Ks[kb_row + kf * 8 + tig + 4]);
                mma_tf32_b(sacc[nf], qa[kf], b0, b1);
            }
        }

        // causal mask (values already scaled)
        #pragma unroll
        for (int nf = 0; nf < 8; nf++) {
            int colb = k0 + nf * 8 + 2 * tig;
            if (colb     > row0g) sacc[nf][0] = -1e30f;
            if (colb + 1 > row0g) sacc[nf][1] = -1e30f;
            if (colb     > row1g) sacc[nf][2] = -1e30f;
            if (colb + 1 > row1g) sacc[nf][3] = -1e30f;
        }

        float rm0 = -1e30f, rm1 = -1e30f;
        #pragma unroll
        for (int nf = 0; nf < 8; nf++) {
            rm0 = fmaxf(rm0, fmaxf(sacc[nf][0], sacc[nf][1]));
            rm1 = fmaxf(rm1, fmaxf(sacc[nf][2], sacc[nf][3]));
        }
        rm0 = fmaxf(rm0, __shfl_xor_sync(0xffffffffu, rm0, 1));
        rm0 = fmaxf(rm0, __shfl_xor_sync(0xffffffffu, rm0, 2));
        rm1 = fmaxf(rm1, __shfl_xor_sync(0xffffffffu, rm1, 1));
        rm1 = fmaxf(rm1, __shfl_xor_sync(0xffffffffu, rm1, 2));
        float nm0 = fmaxf(m0, rm0), nm1 = fmaxf(m1, rm1);
        float corr0 = __expf(m0 - nm0), corr1 = __expf(m1 - nm1);
        float rs0 = 0.f, rs1 = 0.f;
        #pragma unroll
        for (int nf = 0; nf < 8; nf++) {
            float p0 = __expf(sacc[nf][0] - nm0);
            float p1 = __expf(sacc[nf][1] - nm0);
            float p2 = __expf(sacc[nf][2] - nm1);
            float p3 = __expf(sacc[nf][3] - nm1);
            rs0 += p0 + p1; rs1 += p2 + p3;
            sacc[nf][0] = p0; sacc[nf][1] = p1;
            sacc[nf][2] = p2; sacc[nf][3] = p3;
        }
        rs0 += __shfl_xor_sync(0xffffffffu, rs0, 1);
        rs0 += __shfl_xor_sync(0xffffffffu, rs0, 2);
        rs1 += __shfl_xor_sync(0xffffffffu, rs1, 1);
        rs1 += __shfl_xor_sync(0xffffffffu, rs1, 2);
        l0 = l0 * corr0 + rs0;  m0 = nm0;
        l1 = l1 * corr1 + rs1;  m1 = nm1;
        #pragma unroll
        for (int nf = 0; nf < 8; nf++) {
            oacc[nf][0] *= corr0; oacc[nf][1] *= corr0;
            oacc[nf][2] *= corr1; oacc[nf][3] *= corr1;
        }

        // P (tf32-rounded) to warp-private smem strip
        #pragma unroll
        for (int nf = 0; nf < 8; nf++) {
            int cc = nf * 8 + 2 * tig;
            Ph[prow0 + cc]     = rtf32(sacc[nf][0]);
            Ph[prow0 + cc + 1] = rtf32(sacc[nf][1]);
            Ph[prow1 + cc]     = rtf32(sacc[nf][2]);
            Ph[prow1 + cc + 1] = rtf32(sacc[nf][3]);
        }
        __syncwarp();

        // O += P @ V  (single tf32 term)
        #pragma unroll
        for (int kf = 0; kf < 8; kf++) {
            uint32_t ah[4];
            int c = kf * 8 + tig;
            ah[0] = __float_as_uint(Ph[prow0 + c]);
            ah[1] = __float_as_uint(Ph[prow1 + c]);
            ah[2] = __float_as_uint(Ph[prow0 + c + 4]);
            ah[3] = __float_as_uint(Ph[prow1 + c + 4]);
            const int vr0 = (kf * 8 + tig) * 72;
            const int vr1 = (kf * 8 + tig + 4) * 72;
            #pragma unroll
            for (int nf = 0; nf < 8; nf++) {
                int n = nf * 8 + grp;
                uint32_t b0h = __float_as_uint(Vh[vr0 + n]);
                uint32_t b1h = __float_as_uint(Vh[vr1 + n]);
                mma_tf32_b(oacc[nf], ah, b0h, b1h);
            }
        }
    }

    const float inv0 = 1.0f / l0, inv1 = 1.0f / l1;
    const size_t ob0 = (tokbase + row0g) * DMODEL + hh * 64;
    const size_t ob1 = (tokbase + row1g) * DMODEL + hh * 64;
    #pragma unroll
    for (int nf = 0; nf < 8; nf++) {
        int cc = nf * 8 + 2 * tig;
        o[ob0 + cc]     = rtf32(oacc[nf][0] * inv0);
        o[ob0 + cc + 1] = rtf32(oacc[nf][1] * inv0);
        o[ob1 + cc]     = rtf32(oacc[nf][2] * inv1);
        o[ob1 + cc + 1] = rtf32(oacc[nf][3] * inv1);
    }
}

// ---------------------------------------------------------------------------
// Host orchestration (graph-capturable: kernel launches only)
// ---------------------------------------------------------------------------
extern "C" void kernel_launch(void* const* d_in, const int* in_sizes, int n_in,
                              void* d_out, int out_size) {
    const int*   idx   = (const int*)d_in[0];
    const float* wte   = (const float*)d_in[1];
    const float* wpe   = (const float*)d_in[2];
    const float* ln1_w = (const float*)d_in[3];
    const float* ln1_b = (const float*)d_in[4];
    const float* Wqkv  = (const float*)d_in[5];
    const float* bqkv  = (const float*)d_in[6];
    const float* Wproj = (const float*)d_in[7];
    const float* bproj = (const float*)d_in[8];
    const float* ln2_w = (const float*)d_in[9];
    const float* ln2_b = (const float*)d_in[10];
    const float* Wfc   = (const float*)d_in[11];
    const float* bfc   = (const float*)d_in[12];
    const float* Wfc2  = (const float*)d_in[13];
    const float* bfc2  = (const float*)d_in[14];
    const float* lnf_w = (const float*)d_in[15];
    const float* lnf_b = (const float*)d_in[16];
    float* out = (float*)d_out;

    float *x, *h, *qkv, *o, *ff, *w;
    cudaGetSymbolAddress((void**)&x,   g_x);
    cudaGetSymbolAddress((void**)&h,   g_h);
    cudaGetSymbolAddress((void**)&qkv, g_qkv);
    cudaGetSymbolAddress((void**)&o,   g_o);
    cudaGetSymbolAddress((void**)&ff,  g_ff);
    cudaGetSymbolAddress((void**)&w,   g_w);

    cudaFuncSetAttribute(attn_mma_kernel,
                         cudaFuncAttributeMaxDynamicSharedMemorySize, ATTN_SMEM);
    cudaFuncSetAttribute(wgemm_kernel<false, EPI_QKV>,
                         cudaFuncAttributeMaxDynamicSharedMemorySize, WGEMM_SMEM);
    cudaFuncSetAttribute(wgemm_kernel<false, EPI_GELU>,
                         cudaFuncAttributeMaxDynamicSharedMemorySize, WGEMM_SMEM);
    cudaFuncSetAttribute(wgemm_kernel<true, EPI_NONE>,
                         cudaFuncAttributeMaxDynamicSharedMemorySize, WGEMM_SMEM);

    // Pre-round all weights into scratch (tf32, rna)
    rcopy_kernel<<<592, 256>>>(Wqkv,  w + WOFF_QKV,  NLAYER * DMODEL * 3 * DMODEL / 4);
    rcopy_kernel<<<592, 256>>>(Wproj, w + WOFF_PROJ, NLAYER * DMODEL * DMODEL / 4);
    rcopy_kernel<<<592, 256>>>(Wfc,   w + WOFF_FC,   NLAYER * DMODEL * FFDIM / 4);
    rcopy_kernel<<<592, 256>>>(Wfc2,  w + WOFF_FC2,  NLAYER * FFDIM * DMODEL / 4);
    rcopy_kernel<<<1184, 256>>>(wte,  w + WOFF_WTE,  VOCAB * DMODEL / 4);

    embed_kernel<<<(NTOK * DMODEL) / 256, 256>>>(idx, wte, wpe, x);

    for (int l = 0; l < NLAYER; l++) {
        const float* wq  = w + WOFF_QKV  + (size_t)l * DMODEL * 3 * DMODEL;
        const float* bq  = bqkv  + (size_t)l * 3 * DMODEL;
        const float* wp  = w + WOFF_PROJ + (size_t)l * DMODEL * DMODEL;
        const float* bp  = bproj + (size_t)l * DMODEL;
        const float* wf1 = w + WOFF_FC   + (size_t)l * DMODEL * FFDIM;
        const float* bf1 = bfc   + (size_t)l * FFDIM;
        const float* wf2 = w + WOFF_FC2  + (size_t)l * FFDIM * DMODEL;
        const float* bf2 = bfc2  + (size_t)l * DMODEL;

        ln_kernel<<<NTOK, 256>>>(x, ln1_w + l * DMODEL, ln1_b + l * DMODEL, h);

        wgemm_kernel<false, EPI_QKV><<<dim3(NTOK / 128, (3 * DMODEL) / 256), 256, WGEMM_SMEM>>>(
            h, wq, bq, nullptr, qkv, NTOK, 3 * DMODEL, DMODEL);

        attn_mma_kernel<<<dim3(SEQ / 64, NHEAD, NTOK / SEQ), 128, ATTN_SMEM>>>(qkv, o);

        mma_gemm_kernel<EPI_RES><<<dim3(NTOK / 128, DMODEL / 128), 256>>>(
            o, wp, bp, x, x, NTOK, DMODEL, DMODEL);

        ln_kernel<<<NTOK, 256>>>(x, ln2_w + l * DMODEL, ln2_b + l * DMODEL, h);

        wgemm_kernel<false, EPI_GELU><<<dim3(NTOK / 128, FFDIM / 256), 256, WGEMM_SMEM>>>(
            h, wf1, bf1, nullptr, ff, NTOK, FFDIM, DMODEL);

        mma_gemm_kernel<EPI_RES><<<dim3(NTOK / 128, DMODEL / 128), 256>>>(
            ff, wf2, bf2, x, x, NTOK, DMODEL, FFDIM);
    }

    ln_kernel<<<NTOK, 256>>>(x, lnf_w, lnf_b, h);

    // logits = h @ wte_rounded^T  [4096, 50257]
    wgemm_kernel<true, EPI_NONE><<<dim3(NTOK / 128, (VOCAB + 255) / 256), 256, WGEMM_SMEM>>>(
        h, w + WOFF_WTE, nullptr, nullptr, out, NTOK, VOCAB, DMODEL);
}